// round 9
// baseline (speedup 1.0000x reference)
#include <cuda_runtime.h>
#include <cuda_fp16.h>

// ---------------- problem constants ----------------
// B=32, CIN=256, H=W=32 (N=1024), DK=DV=128, HEADS=8, DKH=DVH=16, OUT=256
#define NB    32
#define NPIX  1024
#define NCIN  256

typedef unsigned long long u64;
typedef unsigned int u32;

// ---------------- scratch (static device mem; no allocations allowed) ------
__device__ __half g_qh[32 * 8 * 1024 * 16];   // [bh][n][16]  (pre-scaled 0.25)
__device__ __half g_kh[32 * 8 * 1024 * 16];   // [bh][n][16]
__device__ __half g_vt[32 * 8 * 16 * 1024];   // [bh][d][n]   (transposed)
__device__ float  g_attn[32 * 128 * 1024];    // [b][dv][n]

// ---------------- packed f32x2 helpers -------------------------------------
__device__ __forceinline__ u64 fma2(u64 a, u64 b, u64 c) {
    u64 d;
    asm("fma.rn.f32x2 %0, %1, %2, %3;" : "=l"(d) : "l"(a), "l"(b), "l"(c));
    return d;
}
__device__ __forceinline__ u64 pack2(float lo, float hi) {
    u64 d;
    asm("mov.b64 %0, {%1, %2};" : "=l"(d) : "f"(lo), "f"(hi));
    return d;
}
__device__ __forceinline__ float2 unpack2(u64 v) {
    float2 r;
    asm("mov.b64 {%0, %1}, %2;" : "=f"(r.x), "=f"(r.y) : "l"(v));
    return r;
}
__device__ __forceinline__ void split64(u64 v, u32& lo, u32& hi) {
    asm("mov.b64 {%0, %1}, %2;" : "=r"(lo), "=r"(hi) : "l"(v));
}
__device__ __forceinline__ u64 join64(u32 lo, u32 hi) {
    u64 d;
    asm("mov.b64 %0, {%1, %2};" : "=l"(d) : "r"(lo), "r"(hi));
    return d;
}
__device__ __forceinline__ u64 make2(float v) { return pack2(v, v); }
__device__ __forceinline__ u32 h2u(__half2 h) {
    union { __half2 h; u32 u; } c; c.h = h; return c.u;
}

// ---------------- dual packed exp (magic round + deg-4 poly, FMA pipe) -----
__device__ __forceinline__ u64 exp_dual(u64 s2) {
    const u64 ONE   = make2(1.0f);
    const u64 NEG1  = make2(-1.0f);
    const u64 L2E   = make2(1.4426950408889634f);
    const u64 MAGIC = make2(12582912.0f);            // 2^23 + 2^22
    const u64 C4 = make2(9.6181291e-3f);
    const u64 C3 = make2(5.5504109e-2f);
    const u64 C2 = make2(2.4022651e-1f);
    const u64 C1 = make2(6.9314718e-1f);
    u64 y = fma2(s2, L2E, 0ull);
    u64 r = fma2(y, ONE, MAGIC);
    u64 t = fma2(MAGIC, NEG1, r);
    u64 f = fma2(t, NEG1, y);
    u64 p = fma2(C4, f, C3);
    p = fma2(p, f, C2);
    p = fma2(p, f, C1);
    p = fma2(p, f, ONE);
    u32 rl, rh;
    split64(r, rl, rh);
    u32 sl = (rl + 0xB4C0007Fu) << 23;
    u32 sh = (rh + 0xB4C0007Fu) << 23;
    return fma2(p, join64(sl, sh), 0ull);
}

// ---------------- mma.sync m16n8k16 fp16 -> fp32 ---------------------------
__device__ __forceinline__ void mma16816(float4& c, const u32* a, u32 b0, u32 b1) {
    asm volatile(
        "mma.sync.aligned.m16n8k16.row.col.f32.f16.f16.f32 "
        "{%0,%1,%2,%3}, {%4,%5,%6,%7}, {%8,%9}, {%0,%1,%2,%3};"
        : "+f"(c.x), "+f"(c.y), "+f"(c.z), "+f"(c.w)
        : "r"(a[0]), "r"(a[1]), "r"(a[2]), "r"(a[3]), "r"(b0), "r"(b1));
}

__device__ __forceinline__ void hsplit(float v, __half& hi, __half& lo) {
    hi = __float2half_rn(v);
    lo = __float2half_rn(v - __half2float(hi));
}

// ---------------- kernel 1: tensor-core fused projection -------------------
// C[512m x 1024n] per batch, m-tiles: 0=q 1=k 2=v 3=conv (blockIdx.y).
// fp16 hi/lo 3-term split (Ah*Bh + Al*Bh + Ah*Bl) ~ fp32 accuracy.
// A staged [m][24] halves, B staged n-major [n][24]; conflict-free frag LDS.
// Epilogue stages C through smem alias S with row stride 132 floats
// (132*4 = 528 bytes, 16B-aligned rows -> legal float4 reads).
#define SSTR 132
__global__ __launch_bounds__(256, 2) void k_proj(
    const float* __restrict__ x, const float* __restrict__ w_qkv,
    const float* __restrict__ b_qkv, const float* __restrict__ w_out,
    const float* __restrict__ b_out, float* __restrict__ out)
{
    __shared__ __align__(16) char smraw[24576];
    __half* sAh = (__half*)smraw;            // [128][24]
    __half* sAl = (__half*)smraw + 3072;
    __half* sBh = (__half*)smraw + 6144;     // [128 n][24 k]
    __half* sBl = (__half*)smraw + 9216;
    float*  S   = (float*)smraw;             // epilogue alias [32][SSTR]

    const int b  = blockIdx.z;
    const int mt = blockIdx.y;               // 0=q 1=k 2=v 3=conv
    const int n0 = blockIdx.x * 128;
    const int tid = threadIdx.x;
    const int w    = tid >> 5;
    const int lane = tid & 31;
    const int gid = lane >> 2, tig = lane & 3;
    const int wm = w & 3;                    // m-quarter (32 rows)
    const int wn = w >> 2;                   // n-half (64 cols)
    const float* xb = x + b * (NCIN * NPIX);
    const float* wbase = (mt < 3) ? (w_qkv + mt * 128 * NCIN) : w_out;
    const float wscale = (mt == 0) ? 0.25f : 1.0f;

    const int a_ml0 = tid & 127, a_kq0 = (tid >> 7);
    const int b_kl0 = tid >> 5, b_nl0 = (tid & 31) * 4;

    float4 ar[2], br[2];
    ar[0] = *(const float4*)&wbase[a_ml0 * NCIN + a_kq0 * 4];
    ar[1] = *(const float4*)&wbase[a_ml0 * NCIN + (a_kq0 + 2) * 4];
    br[0] = *(const float4*)&xb[b_kl0 * NPIX + n0 + b_nl0];
    br[1] = *(const float4*)&xb[(b_kl0 + 8) * NPIX + n0 + b_nl0];

    float4 c[2][8];
#pragma unroll
    for (int t = 0; t < 2; ++t)
#pragma unroll
        for (int nb = 0; nb < 8; ++nb) c[t][nb] = make_float4(0.f, 0.f, 0.f, 0.f);

    for (int cs = 0; cs < 16; ++cs) {
        __syncthreads();
        // ---- stage A: [m][24] hi/lo ----
#pragma unroll
        for (int r = 0; r < 2; ++r) {
            int kq = a_kq0 + 2 * r;
            const float* av = (const float*)&ar[r];
#pragma unroll
            for (int j = 0; j < 4; ++j) {
                __half hi, lo;
                hsplit(av[j] * wscale, hi, lo);
                sAh[a_ml0 * 24 + kq * 4 + j] = hi;
                sAl[a_ml0 * 24 + kq * 4 + j] = lo;
            }
        }
        // ---- stage B transposed: [n][24] hi/lo ----
#pragma unroll
        for (int r = 0; r < 2; ++r) {
            int kk = b_kl0 + r * 8;
            const float* bv = (const float*)&br[r];
#pragma unroll
            for (int j = 0; j < 4; ++j) {
                __half hi, lo;
                hsplit(bv[j], hi, lo);
                sBh[(b_nl0 + j) * 24 + kk] = hi;
                sBl[(b_nl0 + j) * 24 + kk] = lo;
            }
        }
        __syncthreads();
        if (cs < 15) {
            int k0 = (cs + 1) * 16;
            ar[0] = *(const float4*)&wbase[a_ml0 * NCIN + k0 + a_kq0 * 4];
            ar[1] = *(const float4*)&wbase[a_ml0 * NCIN + k0 + (a_kq0 + 2) * 4];
            br[0] = *(const float4*)&xb[(k0 + b_kl0) * NPIX + n0 + b_nl0];
            br[1] = *(const float4*)&xb[(k0 + b_kl0 + 8) * NPIX + n0 + b_nl0];
        }

        // ---- fragments (KROW=24 -> 12 words, conflict-free) ----
        const u32* Ahw = (const u32*)sAh;
        const u32* Alw = (const u32*)sAl;
        const u32* Bhw = (const u32*)sBh;
        const u32* Blw = (const u32*)sBl;

        u32 ah[2][4], al[2][4];
#pragma unroll
        for (int t = 0; t < 2; ++t) {
            int r0 = wm * 32 + t * 16 + gid;
            ah[t][0] = Ahw[r0 * 12 + tig];
            ah[t][1] = Ahw[(r0 + 8) * 12 + tig];
            ah[t][2] = Ahw[r0 * 12 + tig + 4];
            ah[t][3] = Ahw[(r0 + 8) * 12 + tig + 4];
            al[t][0] = Alw[r0 * 12 + tig];
            al[t][1] = Alw[(r0 + 8) * 12 + tig];
            al[t][2] = Alw[r0 * 12 + tig + 4];
            al[t][3] = Alw[(r0 + 8) * 12 + tig + 4];
        }
        u32 bf[8][2];
#pragma unroll
        for (int nb = 0; nb < 8; ++nb) {
            int n = wn * 64 + nb * 8 + gid;
            bf[nb][0] = Bhw[n * 12 + tig];
            bf[nb][1] = Bhw[n * 12 + tig + 4];
        }
#pragma unroll
        for (int nb = 0; nb < 8; ++nb) {
            mma16816(c[0][nb], ah[0], bf[nb][0], bf[nb][1]);
            mma16816(c[1][nb], ah[1], bf[nb][0], bf[nb][1]);
            mma16816(c[0][nb], al[0], bf[nb][0], bf[nb][1]);
            mma16816(c[1][nb], al[1], bf[nb][0], bf[nb][1]);
        }
#pragma unroll
        for (int nb = 0; nb < 8; ++nb) {
            int n = wn * 64 + nb * 8 + gid;
            bf[nb][0] = Blw[n * 12 + tig];
            bf[nb][1] = Blw[n * 12 + tig + 4];
        }
#pragma unroll
        for (int nb = 0; nb < 8; ++nb) {
            mma16816(c[0][nb], ah[0], bf[nb][0], bf[nb][1]);
            mma16816(c[1][nb], ah[1], bf[nb][0], bf[nb][1]);
        }
    }

    // ---- bias (q-bias pre-scaled 0.25 to match w scaling) ----
    float bias[2][2];
#pragma unroll
    for (int t = 0; t < 2; ++t) {
        int m = wm * 32 + t * 16 + gid;
        if (mt < 3) {
            bias[t][0] = b_qkv[mt * 128 + m] * wscale;
            bias[t][1] = b_qkv[mt * 128 + m + 8] * wscale;
        } else {
            bias[t][0] = b_out[m];
            bias[t][1] = b_out[m + 8];
        }
    }
#pragma unroll
    for (int t = 0; t < 2; ++t)
#pragma unroll
        for (int nb = 0; nb < 8; ++nb) {
            c[t][nb].x += bias[t][0]; c[t][nb].y += bias[t][0];
            c[t][nb].z += bias[t][1]; c[t][nb].w += bias[t][1];
        }

    // ---- epilogue: 4 chunks of 32 m-rows through smem ----
    for (int mc = 0; mc < 4; ++mc) {
        __syncthreads();
        if (wm == mc) {
#pragma unroll
            for (int t = 0; t < 2; ++t)
#pragma unroll
                for (int nb = 0; nb < 8; ++nb) {
                    int col = wn * 64 + nb * 8 + tig * 2;
                    int r0 = t * 16 + gid;
                    *(float2*)&S[r0 * SSTR + col]       = make_float2(c[t][nb].x, c[t][nb].y);
                    *(float2*)&S[(r0 + 8) * SSTR + col] = make_float2(c[t][nb].z, c[t][nb].w);
                }
        }
        __syncthreads();

        if (mt == 3) {              // conv -> d_out channels 0..127 (fp32)
#pragma unroll
            for (int t = 0; t < 4; ++t) {
                int idx = tid + t * 256;
                int nq = idx & 31, row = idx >> 5;
                float4 v = *(const float4*)&S[row * SSTR + nq * 4];
                *(float4*)&out[b * 262144 + (mc * 32 + row) * NPIX + n0 + nq * 4] = v;
            }
        } else if (mt == 2) {       // V transposed fp16: [bh][d][n]
#pragma unroll
            for (int t = 0; t < 2; ++t) {
                int idx = tid + t * 256;
                int noct = idx & 15, row = idx >> 4;   // row 0..31
                const float* sp = &S[row * SSTR + noct * 8];
                uint4 u;
                u.x = h2u(__floats2half2_rn(sp[0], sp[1]));
                u.y = h2u(__floats2half2_rn(sp[2], sp[3]));
                u.z = h2u(__floats2half2_rn(sp[4], sp[5]));
                u.w = h2u(__floats2half2_rn(sp[6], sp[7]));
                int h = mc * 2 + (row >> 4);
                int d = row & 15;
                *(uint4*)&g_vt[(((b * 8 + h) * 16 + d) << 10) + n0 + noct * 8] = u;
            }
        } else {                    // q / k fp16: [bh][n][16]
            __half* g = (mt == 0) ? g_qh : g_kh;
#pragma unroll
            for (int t = 0; t < 2; ++t) {
                int idx = tid + t * 256;
                int n = idx & 127;
                int rest = idx >> 7;            // 0..3
                int hsel = rest >> 1, dh = rest & 1;
                int rb = hsel * 16 + dh * 8;
                uint4 u;
                u.x = h2u(__floats2half2_rn(S[(rb + 0) * SSTR + n], S[(rb + 1) * SSTR + n]));
                u.y = h2u(__floats2half2_rn(S[(rb + 2) * SSTR + n], S[(rb + 3) * SSTR + n]));
                u.z = h2u(__floats2half2_rn(S[(rb + 4) * SSTR + n], S[(rb + 5) * SSTR + n]));
                u.w = h2u(__floats2half2_rn(S[(rb + 6) * SSTR + n], S[(rb + 7) * SSTR + n]));
                int bh = b * 8 + mc * 2 + hsel;
                *(uint4*)&g[((u64)bh << 14) + (u64)(n0 + n) * 16 + dh * 8] = u;
            }
        }
    }
}

// ---------------- kernel 2: tensor-core attention (unchanged, R7) ----------
#define KROW 24       // halves per Ks row (12 words, conflict-free frags)
#define VROW 1032     // halves per Vt row (516 words)
__global__ __launch_bounds__(256, 2) void k_attn()
{
    extern __shared__ __half sm[];
    __half* Ks = sm;                    // [1024][KROW]
    __half* Vt = sm + 1024 * KROW;      // [16][VROW]
    const int qb  = blockIdx.x;
    const int bh  = blockIdx.y;
    const int tid = threadIdx.x;
    const int w   = tid >> 5;
    const int lane = tid & 31;
    const int gid = lane >> 2, tig = lane & 3;
    const u64 ONE = make2(1.0f);

    const uint4* ksrc = (const uint4*)(g_kh + ((u64)bh << 14));
    const uint4* vsrc = (const uint4*)(g_vt + ((u64)bh << 14));
#pragma unroll
    for (int j = 0; j < 8; ++j) {
        int idx = tid + j * 256;
        int seq = idx >> 1, hp = idx & 1;
        *(uint4*)&Ks[seq * KROW + hp * 8] = ksrc[idx];
    }
#pragma unroll
    for (int j = 0; j < 8; ++j) {
        int idx = tid + j * 256;
        int row = idx >> 7, off = (idx & 127) * 8;
        *(uint4*)&Vt[row * VROW + off] = vsrc[idx];
    }

    const __half* qp = g_qh + ((u64)bh << 14) + (qb * 128 + w * 16) * 16;
    u32 aq[4];
    aq[0] = *(const u32*)(qp + gid * 16 + tig * 2);
    aq[1] = *(const u32*)(qp + (gid + 8) * 16 + tig * 2);
    aq[2] = *(const u32*)(qp + gid * 16 + tig * 2 + 8);
    aq[3] = *(const u32*)(qp + (gid + 8) * 16 + tig * 2 + 8);
    __syncthreads();

    float4 o0 = make_float4(0.f, 0.f, 0.f, 0.f);
    float4 o1 = make_float4(0.f, 0.f, 0.f, 0.f);
    u64 l2a = 0ull, l2b = 0ull;

    const u32* kw = (const u32*)Ks;
    const u32* vw = (const u32*)Vt;

#pragma unroll 2
    for (int n0 = 0; n0 < NPIX; n0 += 16) {
        u32 kb00 = kw[(n0 + gid) * 12 + tig];
        u32 kb01 = kw[(n0 + gid) * 12 + tig + 4];
        u32 kb10 = kw[(n0 + 8 + gid) * 12 + tig];
        u32 kb11 = kw[(n0 + 8 + gid) * 12 + tig + 4];
        float4 s0 = make_float4(0.f, 0.f, 0.f, 0.f);
        float4 s1 = make_float4(0.f, 0.f, 0.f, 0.f);
        mma16816(s0, aq, kb00, kb01);
        mma16816(s1, aq, kb10, kb11);

        u64 e0 = exp_dual(pack2(s0.x, s0.y));
        u64 e1 = exp_dual(pack2(s0.z, s0.w));
        u64 e2 = exp_dual(pack2(s1.x, s1.y));
        u64 e3 = exp_dual(pack2(s1.z, s1.w));
        l2a = fma2(e0, ONE, l2a); l2a = fma2(e2, ONE, l2a);
        l2b = fma2(e1, ONE, l2b); l2b = fma2(e3, ONE, l2b);

        float2 f0 = unpack2(e0), f1 = unpack2(e1), f2 = unpack2(e2), f3 = unpack2(e3);
        __half2 h0 = __floats2half2_rn(f0.x, f0.y);
        __half2 h1 = __floats2half2_rn(f1.x, f1.y);
        __half2 h2 = __floats2half2_rn(f2.x, f2.y);
        __half2 h3 = __floats2half2_rn(f3.x, f3.y);
        float2 r0 = __half22float2(h0), r1 = __half22float2(h1);
        float2 r2 = __half22float2(h2), r3 = __half22float2(h3);
        u32 ph[4] = {h2u(h0), h2u(h1), h2u(h2), h2u(h3)};
        u32 pl[4] = {h2u(__floats2half2_rn(f0.x - r0.x, f0.y - r0.y)),
                     h2u(__floats2half2_rn(f1.x - r1.x, f1.y - r1.y)),
                     h2u(__floats2half2_rn(f2.x - r2.x, f2.y - r2.y)),
                     h2u(__floats2half2_rn(f3.x - r3.x, f3.y - r3.y))};

        u32 vb00 = vw[gid * 516 + (n0 >> 1) + tig];
        u32 vb01 = vw[gid * 516 + (n0 >> 1) + tig + 4];
        u32 vb10 = vw[(gid + 8) * 516 + (n0 >> 1) + tig];
        u32 vb11 = vw[(gid + 8) * 516 + (n0 >> 1) + tig + 4];

        mma16816(o0, ph, vb00, vb01);
        mma16816(o0, pl, vb00, vb01);
        mma16816(o1, ph, vb10, vb11);
        mma16816(o1, pl, vb10, vb11);
    }

    float2 lA = unpack2(l2a), lB = unpack2(l2b);
    float lr0 = lA.x + lA.y;
    float lr8 = lB.x + lB.y;
    lr0 += __shfl_xor_sync(0xFFFFFFFFu, lr0, 1);
    lr0 += __shfl_xor_sync(0xFFFFFFFFu, lr0, 2);
    lr8 += __shfl_xor_sync(0xFFFFFFFFu, lr8, 1);
    lr8 += __shfl_xor_sync(0xFFFFFFFFu, lr8, 2);
    float i0 = 1.0f / lr0, i8 = 1.0f / lr8;

    const int b = bh >> 3, h = bh & 7;
    float* ob = g_attn + b * (128 * NPIX) + h * (16 * NPIX);
    const int seq0 = qb * 128 + w * 16 + gid;
    const int d0 = tig * 2;
    ob[(d0 + 0) * NPIX + seq0]     = o0.x * i0;
    ob[(d0 + 1) * NPIX + seq0]     = o0.y * i0;
    ob[(d0 + 0) * NPIX + seq0 + 8] = o0.z * i8;
    ob[(d0 + 1) * NPIX + seq0 + 8] = o0.w * i8;
    ob[(d0 + 8) * NPIX + seq0]     = o1.x * i0;
    ob[(d0 + 9) * NPIX + seq0]     = o1.y * i0;
    ob[(d0 + 8) * NPIX + seq0 + 8] = o1.z * i8;
    ob[(d0 + 9) * NPIX + seq0 + 8] = o1.w * i8;
}

// ---------------- kernel 3: attn output projection (unchanged, FFMA2) ------
__global__ __launch_bounds__(256, 2) void k_attnproj(
    const float* __restrict__ w_attn, const float* __restrict__ b_attn,
    float* __restrict__ out)
{
    __shared__ float As[16][128];
    __shared__ float Bs[16][128];
    const int b  = blockIdx.z;
    const int n0 = blockIdx.x * 128;
    const int tid = threadIdx.x;
    const int tx = tid & 15;
    const int ty = tid >> 4;
    const float* Bsrc = g_attn + b * (128 * NPIX);

    const int a_ml0 = tid & 127, a_kq0 = (tid >> 7);
    const int b_kl0 = tid >> 5, b_nl0 = (tid & 31) * 4;

    float4 ar[2], br[2];
    ar[0] = *(const float4*)&w_attn[a_ml0 * 128 + a_kq0 * 4];
    ar[1] = *(const float4*)&w_attn[a_ml0 * 128 + (a_kq0 + 2) * 4];
    br[0] = *(const float4*)&Bsrc[b_kl0 * NPIX + n0 + b_nl0];
    br[1] = *(const float4*)&Bsrc[(b_kl0 + 8) * NPIX + n0 + b_nl0];

    u64 acc[8][4];
#pragma unroll
    for (int i = 0; i < 8; ++i)
#pragma unroll
        for (int j = 0; j < 4; ++j) acc[i][j] = 0ull;

    for (int c = 0; c < 8; ++c) {
        __syncthreads();
#pragma unroll
        for (int r = 0; r < 2; ++r) {
            int kq = a_kq0 + r * 2;
            As[kq * 4 + 0][a_ml0] = ((float*)&ar[r])[0];
            As[kq * 4 + 1][a_ml0] = ((float*)&ar[r])[1];
            As[kq * 4 + 2][a_ml0] = ((float*)&ar[r])[2];
            As[kq * 4 + 3][a_ml0] = ((float*)&ar[r])[3];
        }
        *(float4*)&Bs[b_kl0][b_nl0]     = br[0];
        *(float4*)&Bs[b_kl0 + 8][b_nl0] = br[1];
        __syncthreads();
        if (c < 7) {
            int k0 = (c + 1) * 16;
            ar[0] = *(const float4*)&w_attn[a_ml0 * 128 + k0 + a_kq0 * 4];
            ar[1] = *(const float4*)&w_attn[a_ml0 * 128 + k0 + (a_kq0 + 2) * 4];
            br[0] = *(const float4*)&Bsrc[(k0 + b_kl0) * NPIX + n0 + b_nl0];
            br[1] = *(const float4*)&Bsrc[(k0 + b_kl0 + 8) * NPIX + n0 + b_nl0];
        }
#pragma unroll
        for (int kk = 0; kk < 16; ++kk) {
            float4 a0 = *(const float4*)&As[kk][ty * 8];
            float4 a1 = *(const float4*)&As[kk][ty * 8 + 4];
            ulonglong2 b01 = *(const ulonglong2*)&Bs[kk][tx * 8];
            ulonglong2 b23 = *(const ulonglong2*)&Bs[kk][tx * 8 + 4];
            u64 bp[4] = {b01.x, b01.y, b23.x, b23.y};
            float am[8] = {a0.x, a0.y, a0.z, a0.w, a1.x, a1.y, a1.z, a1.w};
#pragma unroll
            for (int i = 0; i < 8; ++i) {
                u64 ad = pack2(am[i], am[i]);
#pragma unroll
                for (int j = 0; j < 4; ++j)
                    acc[i][j] = fma2(ad, bp[j], acc[i][j]);
            }
        }
    }

#pragma unroll
    for (int i = 0; i < 8; ++i) {
        int m = ty * 8 + i;
        float bias = b_attn[m];
        float v[8];
#pragma unroll
        for (int j = 0; j < 4; ++j) {
            float2 t = unpack2(acc[i][j]);
            v[j * 2 + 0] = t.x + bias;
            v[j * 2 + 1] = t.y + bias;
        }
        float* dst = out + b * 262144 + (128 + m) * NPIX + n0 + tx * 8;
        *(float4*)dst       = make_float4(v[0], v[1], v[2], v[3]);
        *(float4*)(dst + 4) = make_float4(v[4], v[5], v[6], v[7]);
    }
}

// ---------------- launch ----------------------------------------------------
extern "C" void kernel_launch(void* const* d_in, const int* in_sizes, int n_in,
                              void* d_out, int out_size)
{
    const float* x      = (const float*)d_in[0];
    const float* w_qkv  = (const float*)d_in[1];
    const float* b_qkv  = (const float*)d_in[2];
    const float* w_attn = (const float*)d_in[3];
    const float* b_attn = (const float*)d_in[4];
    const float* w_out  = (const float*)d_in[5];
    const float* b_out  = (const float*)d_in[6];
    float* out = (float*)d_out;

    dim3 g1(8, 4, 32);                 // n-tiles(128), m-tiles(q/k/v/conv), batch
    k_proj<<<g1, 256>>>(x, w_qkv, b_qkv, w_out, b_out, out);

    const int smem_attn = (1024 * KROW + 16 * VROW) * (int)sizeof(__half); // 82176
    cudaFuncSetAttribute(k_attn, cudaFuncAttributeMaxDynamicSharedMemorySize,
                         smem_attn);
    dim3 g2(8, 256);                   // q-blocks x (b,h)
    k_attn<<<g2, 256, smem_attn>>>();

    dim3 g3(8, 1, 32);
    k_attnproj<<<g3, 256>>>(w_attn, b_attn, out);
}

// round 10
// speedup vs baseline: 1.4472x; 1.4472x over previous
#include <cuda_runtime.h>
#include <cuda_fp16.h>

// ---------------- problem constants ----------------
// B=32, CIN=256, H=W=32 (N=1024), DK=DV=128, HEADS=8, DKH=DVH=16, OUT=256
#define NB    32
#define NPIX  1024
#define NCIN  256

typedef unsigned long long u64;
typedef unsigned int u32;

// ---------------- scratch (static device mem; no allocations allowed) ------
__device__ __half g_qh[32 * 8 * 1024 * 16];   // [bh][n][16]  (pre-scaled 0.25)
__device__ __half g_kh[32 * 8 * 1024 * 16];   // [bh][n][16]
__device__ __half g_vt[32 * 8 * 16 * 1024];   // [bh][d][n]   (transposed)
__device__ float  g_attn[32 * 128 * 1024];    // [b][dv][n]
// pre-converted hi/lo fp16 operands (chunk-major for coalesced staging)
__device__ __half g_wh[4 * 16 * 128 * 16];    // [mt][cs][128m][16k]
__device__ __half g_wl[4 * 16 * 128 * 16];
__device__ __half g_xh[32 * 16 * 1024 * 16];  // [b][cs][1024n][16k]
__device__ __half g_xl[32 * 16 * 1024 * 16];

// ---------------- packed f32x2 helpers -------------------------------------
__device__ __forceinline__ u64 fma2(u64 a, u64 b, u64 c) {
    u64 d;
    asm("fma.rn.f32x2 %0, %1, %2, %3;" : "=l"(d) : "l"(a), "l"(b), "l"(c));
    return d;
}
__device__ __forceinline__ u64 pack2(float lo, float hi) {
    u64 d;
    asm("mov.b64 %0, {%1, %2};" : "=l"(d) : "f"(lo), "f"(hi));
    return d;
}
__device__ __forceinline__ float2 unpack2(u64 v) {
    float2 r;
    asm("mov.b64 {%0, %1}, %2;" : "=f"(r.x), "=f"(r.y) : "l"(v));
    return r;
}
__device__ __forceinline__ void split64(u64 v, u32& lo, u32& hi) {
    asm("mov.b64 {%0, %1}, %2;" : "=r"(lo), "=r"(hi) : "l"(v));
}
__device__ __forceinline__ u64 join64(u32 lo, u32 hi) {
    u64 d;
    asm("mov.b64 %0, {%1, %2};" : "=l"(d) : "r"(lo), "r"(hi));
    return d;
}
__device__ __forceinline__ u64 make2(float v) { return pack2(v, v); }
__device__ __forceinline__ u32 h2u(__half2 h) {
    union { __half2 h; u32 u; } c; c.h = h; return c.u;
}

// ---------------- dual packed exp (magic round + deg-4 poly, FMA pipe) -----
__device__ __forceinline__ u64 exp_dual(u64 s2) {
    const u64 ONE   = make2(1.0f);
    const u64 NEG1  = make2(-1.0f);
    const u64 L2E   = make2(1.4426950408889634f);
    const u64 MAGIC = make2(12582912.0f);            // 2^23 + 2^22
    const u64 C4 = make2(9.6181291e-3f);
    const u64 C3 = make2(5.5504109e-2f);
    const u64 C2 = make2(2.4022651e-1f);
    const u64 C1 = make2(6.9314718e-1f);
    u64 y = fma2(s2, L2E, 0ull);
    u64 r = fma2(y, ONE, MAGIC);
    u64 t = fma2(MAGIC, NEG1, r);
    u64 f = fma2(t, NEG1, y);
    u64 p = fma2(C4, f, C3);
    p = fma2(p, f, C2);
    p = fma2(p, f, C1);
    p = fma2(p, f, ONE);
    u32 rl, rh;
    split64(r, rl, rh);
    u32 sl = (rl + 0xB4C0007Fu) << 23;
    u32 sh = (rh + 0xB4C0007Fu) << 23;
    return fma2(p, join64(sl, sh), 0ull);
}

// ---------------- mma.sync m16n8k16 fp16 -> fp32 ---------------------------
__device__ __forceinline__ void mma16816(float4& c, const u32* a, u32 b0, u32 b1) {
    asm volatile(
        "mma.sync.aligned.m16n8k16.row.col.f32.f16.f16.f32 "
        "{%0,%1,%2,%3}, {%4,%5,%6,%7}, {%8,%9}, {%0,%1,%2,%3};"
        : "+f"(c.x), "+f"(c.y), "+f"(c.z), "+f"(c.w)
        : "r"(a[0]), "r"(a[1]), "r"(a[2]), "r"(a[3]), "r"(b0), "r"(b1));
}

__device__ __forceinline__ void hsplit(float v, __half& hi, __half& lo) {
    hi = __float2half_rn(v);
    lo = __float2half_rn(v - __half2float(hi));
}

// ---------------- pre-pass: convert weights to hi/lo fp16 chunk-major ------
// grid 512 (virtual m), block 64 (k/4). q rows (m<128) pre-scaled by 0.25.
__global__ void k_cvt_w(const float* __restrict__ w_qkv,
                        const float* __restrict__ w_out)
{
    const int m = blockIdx.x;
    const int k0 = threadIdx.x * 4;
    const float* src = (m < 384) ? &w_qkv[m * NCIN + k0]
                                 : &w_out[(m - 384) * NCIN + k0];
    const float sc = (m < 128) ? 0.25f : 1.0f;
    float4 v = *(const float4*)src;
    __half h[4], l[4];
    hsplit(v.x * sc, h[0], l[0]);
    hsplit(v.y * sc, h[1], l[1]);
    hsplit(v.z * sc, h[2], l[2]);
    hsplit(v.w * sc, h[3], l[3]);
    const int mt = m >> 7, ml = m & 127, cs = k0 >> 4, ko = k0 & 15;
    const int dst = ((mt * 16 + cs) * 128 + ml) * 16 + ko;
    *(uint2*)&g_wh[dst] = *(uint2*)h;
    *(uint2*)&g_wl[dst] = *(uint2*)l;
}

// ---------------- pre-pass: transpose+convert x to hi/lo chunk-major -------
// x [b][256c][1024n] -> g_xh/g_xl [b][cs=c/16][n][16]. grid(64, 32), block 256.
__global__ __launch_bounds__(256) void k_cvt_x(const float* __restrict__ x)
{
    __shared__ float tile[16][260];
    const int cc = blockIdx.x >> 2;          // k-chunk 0..15
    const int ng = blockIdx.x & 3;           // n-group (256 cols)
    const int b  = blockIdx.y;
    const int tid = threadIdx.x;
#pragma unroll
    for (int i = 0; i < 4; ++i) {
        int idx = tid + i * 256;             // 0..1023
        int r = idx >> 6, c4 = (idx & 63) * 4;
        float4 v = *(const float4*)&x[b * (NCIN * NPIX) + (cc * 16 + r) * NPIX
                                      + ng * 256 + c4];
        tile[r][c4 + 0] = v.x; tile[r][c4 + 1] = v.y;
        tile[r][c4 + 2] = v.z; tile[r][c4 + 3] = v.w;
    }
    __syncthreads();
    __half h[16], l[16];
#pragma unroll
    for (int k = 0; k < 16; ++k) hsplit(tile[k][tid], h[k], l[k]);
    const int dst = ((b * 16 + cc) * 1024 + ng * 256 + tid) * 16;
    *(uint4*)&g_xh[dst]     = *(uint4*)&h[0];
    *(uint4*)&g_xh[dst + 8] = *(uint4*)&h[8];
    *(uint4*)&g_xl[dst]     = *(uint4*)&l[0];
    *(uint4*)&g_xl[dst + 8] = *(uint4*)&l[8];
}

// ---------------- kernel 1: tensor-core fused projection -------------------
// Operands pre-converted; staging is pure vector copy. 3-term hi/lo split.
#define SSTR 132
__global__ __launch_bounds__(256, 2) void k_proj(
    const float* __restrict__ b_qkv, const float* __restrict__ b_out,
    float* __restrict__ out)
{
    __shared__ __align__(16) char smraw[24576];
    __half* sAh = (__half*)smraw;            // [128 m][24]
    __half* sAl = (__half*)smraw + 3072;
    __half* sBh = (__half*)smraw + 6144;     // [128 n][24]
    __half* sBl = (__half*)smraw + 9216;
    float*  S   = (float*)smraw;             // epilogue alias [32][SSTR]

    const int b  = blockIdx.z;
    const int mt = blockIdx.y;               // 0=q 1=k 2=v 3=conv
    const int n0 = blockIdx.x * 128;
    const int tid = threadIdx.x;
    const int w    = tid >> 5;
    const int lane = tid & 31;
    const int gid = lane >> 2, tig = lane & 3;
    const int wm = w & 3;                    // m-quarter (32 rows)
    const int wn = w >> 2;                   // n-half (64 cols)

    // staging coords: each thread one uint4 (8 halves) per buffer
    const int sm_row = tid >> 1;             // m or n row 0..127
    const int sm_hp  = tid & 1;              // which 8-half group of chunk

    const __half* wsrch = g_wh + (mt * 16) * 128 * 16;
    const __half* wsrcl = g_wl + (mt * 16) * 128 * 16;
    const __half* xsrch = g_xh + ((u64)b * 16) * 1024 * 16;
    const __half* xsrcl = g_xl + ((u64)b * 16) * 1024 * 16;
    const int aoff = sm_row * 16 + sm_hp * 8;
    const int boff = (n0 + sm_row) * 16 + sm_hp * 8;

    uint4 pah, pal, pbh, pbl;
    pah = *(const uint4*)&wsrch[aoff];
    pal = *(const uint4*)&wsrcl[aoff];
    pbh = *(const uint4*)&xsrch[boff];
    pbl = *(const uint4*)&xsrcl[boff];

    float4 c[2][8];
#pragma unroll
    for (int t = 0; t < 2; ++t)
#pragma unroll
        for (int nb = 0; nb < 8; ++nb) c[t][nb] = make_float4(0.f, 0.f, 0.f, 0.f);

    for (int cs = 0; cs < 16; ++cs) {
        __syncthreads();
        *(uint4*)&sAh[sm_row * 24 + sm_hp * 8] = pah;
        *(uint4*)&sAl[sm_row * 24 + sm_hp * 8] = pal;
        *(uint4*)&sBh[sm_row * 24 + sm_hp * 8] = pbh;
        *(uint4*)&sBl[sm_row * 24 + sm_hp * 8] = pbl;
        __syncthreads();
        if (cs < 15) {
            const int anext = (cs + 1) * 128 * 16 + aoff;
            const int bnext = (cs + 1) * 1024 * 16 + boff;
            pah = *(const uint4*)&wsrch[anext];
            pal = *(const uint4*)&wsrcl[anext];
            pbh = *(const uint4*)&xsrch[bnext];
            pbl = *(const uint4*)&xsrcl[bnext];
        }

        const u32* Ahw = (const u32*)sAh;
        const u32* Alw = (const u32*)sAl;
        const u32* Bhw = (const u32*)sBh;
        const u32* Blw = (const u32*)sBl;

        u32 ah[2][4], al[2][4];
#pragma unroll
        for (int t = 0; t < 2; ++t) {
            int r0 = wm * 32 + t * 16 + gid;
            ah[t][0] = Ahw[r0 * 12 + tig];
            ah[t][1] = Ahw[(r0 + 8) * 12 + tig];
            ah[t][2] = Ahw[r0 * 12 + tig + 4];
            ah[t][3] = Ahw[(r0 + 8) * 12 + tig + 4];
            al[t][0] = Alw[r0 * 12 + tig];
            al[t][1] = Alw[(r0 + 8) * 12 + tig];
            al[t][2] = Alw[r0 * 12 + tig + 4];
            al[t][3] = Alw[(r0 + 8) * 12 + tig + 4];
        }
        u32 bf[8][2];
#pragma unroll
        for (int nb = 0; nb < 8; ++nb) {
            int n = wn * 64 + nb * 8 + gid;
            bf[nb][0] = Bhw[n * 12 + tig];
            bf[nb][1] = Bhw[n * 12 + tig + 4];
        }
#pragma unroll
        for (int nb = 0; nb < 8; ++nb) {
            mma16816(c[0][nb], ah[0], bf[nb][0], bf[nb][1]);
            mma16816(c[1][nb], ah[1], bf[nb][0], bf[nb][1]);
            mma16816(c[0][nb], al[0], bf[nb][0], bf[nb][1]);
            mma16816(c[1][nb], al[1], bf[nb][0], bf[nb][1]);
        }
#pragma unroll
        for (int nb = 0; nb < 8; ++nb) {
            int n = wn * 64 + nb * 8 + gid;
            bf[nb][0] = Blw[n * 12 + tig];
            bf[nb][1] = Blw[n * 12 + tig + 4];
        }
#pragma unroll
        for (int nb = 0; nb < 8; ++nb) {
            mma16816(c[0][nb], ah[0], bf[nb][0], bf[nb][1]);
            mma16816(c[1][nb], ah[1], bf[nb][0], bf[nb][1]);
        }
    }

    // ---- bias (q-bias pre-scaled 0.25 to match w scaling) ----
    const float wscale = (mt == 0) ? 0.25f : 1.0f;
    float bias[2][2];
#pragma unroll
    for (int t = 0; t < 2; ++t) {
        int m = wm * 32 + t * 16 + gid;
        if (mt < 3) {
            bias[t][0] = b_qkv[mt * 128 + m] * wscale;
            bias[t][1] = b_qkv[mt * 128 + m + 8] * wscale;
        } else {
            bias[t][0] = b_out[m];
            bias[t][1] = b_out[m + 8];
        }
    }
#pragma unroll
    for (int t = 0; t < 2; ++t)
#pragma unroll
        for (int nb = 0; nb < 8; ++nb) {
            c[t][nb].x += bias[t][0]; c[t][nb].y += bias[t][0];
            c[t][nb].z += bias[t][1]; c[t][nb].w += bias[t][1];
        }

    // ---- epilogue: 4 chunks of 32 m-rows through smem (R9-verified) ----
    for (int mc = 0; mc < 4; ++mc) {
        __syncthreads();
        if (wm == mc) {
#pragma unroll
            for (int t = 0; t < 2; ++t)
#pragma unroll
                for (int nb = 0; nb < 8; ++nb) {
                    int col = wn * 64 + nb * 8 + tig * 2;
                    int r0 = t * 16 + gid;
                    *(float2*)&S[r0 * SSTR + col]       = make_float2(c[t][nb].x, c[t][nb].y);
                    *(float2*)&S[(r0 + 8) * SSTR + col] = make_float2(c[t][nb].z, c[t][nb].w);
                }
        }
        __syncthreads();

        if (mt == 3) {              // conv -> d_out channels 0..127 (fp32)
#pragma unroll
            for (int t = 0; t < 4; ++t) {
                int idx = tid + t * 256;
                int nq = idx & 31, row = idx >> 5;
                float4 v = *(const float4*)&S[row * SSTR + nq * 4];
                *(float4*)&out[b * 262144 + (mc * 32 + row) * NPIX + n0 + nq * 4] = v;
            }
        } else if (mt == 2) {       // V transposed fp16: [bh][d][n]
#pragma unroll
            for (int t = 0; t < 2; ++t) {
                int idx = tid + t * 256;
                int noct = idx & 15, row = idx >> 4;   // row 0..31
                const float* sp = &S[row * SSTR + noct * 8];
                uint4 u;
                u.x = h2u(__floats2half2_rn(sp[0], sp[1]));
                u.y = h2u(__floats2half2_rn(sp[2], sp[3]));
                u.z = h2u(__floats2half2_rn(sp[4], sp[5]));
                u.w = h2u(__floats2half2_rn(sp[6], sp[7]));
                int h = mc * 2 + (row >> 4);
                int d = row & 15;
                *(uint4*)&g_vt[(((b * 8 + h) * 16 + d) << 10) + n0 + noct * 8] = u;
            }
        } else {                    // q / k fp16: [bh][n][16]
            __half* g = (mt == 0) ? g_qh : g_kh;
#pragma unroll
            for (int t = 0; t < 2; ++t) {
                int idx = tid + t * 256;
                int n = idx & 127;
                int rest = idx >> 7;            // 0..3
                int hsel = rest >> 1, dh = rest & 1;
                int rb = hsel * 16 + dh * 8;
                uint4 u;
                u.x = h2u(__floats2half2_rn(S[(rb + 0) * SSTR + n], S[(rb + 1) * SSTR + n]));
                u.y = h2u(__floats2half2_rn(S[(rb + 2) * SSTR + n], S[(rb + 3) * SSTR + n]));
                u.z = h2u(__floats2half2_rn(S[(rb + 4) * SSTR + n], S[(rb + 5) * SSTR + n]));
                u.w = h2u(__floats2half2_rn(S[(rb + 6) * SSTR + n], S[(rb + 7) * SSTR + n]));
                int bh = b * 8 + mc * 2 + hsel;
                *(uint4*)&g[((u64)bh << 14) + (u64)(n0 + n) * 16 + dh * 8] = u;
            }
        }
    }
}

// ---------------- kernel 2: tensor-core attention (unchanged, R7) ----------
#define KROW 24       // halves per Ks row (12 words, conflict-free frags)
#define VROW 1032     // halves per Vt row (516 words)
__global__ __launch_bounds__(256, 2) void k_attn()
{
    extern __shared__ __half sm[];
    __half* Ks = sm;                    // [1024][KROW]
    __half* Vt = sm + 1024 * KROW;      // [16][VROW]
    const int qb  = blockIdx.x;
    const int bh  = blockIdx.y;
    const int tid = threadIdx.x;
    const int w   = tid >> 5;
    const int lane = tid & 31;
    const int gid = lane >> 2, tig = lane & 3;
    const u64 ONE = make2(1.0f);

    const uint4* ksrc = (const uint4*)(g_kh + ((u64)bh << 14));
    const uint4* vsrc = (const uint4*)(g_vt + ((u64)bh << 14));
#pragma unroll
    for (int j = 0; j < 8; ++j) {
        int idx = tid + j * 256;
        int seq = idx >> 1, hp = idx & 1;
        *(uint4*)&Ks[seq * KROW + hp * 8] = ksrc[idx];
    }
#pragma unroll
    for (int j = 0; j < 8; ++j) {
        int idx = tid + j * 256;
        int row = idx >> 7, off = (idx & 127) * 8;
        *(uint4*)&Vt[row * VROW + off] = vsrc[idx];
    }

    const __half* qp = g_qh + ((u64)bh << 14) + (qb * 128 + w * 16) * 16;
    u32 aq[4];
    aq[0] = *(const u32*)(qp + gid * 16 + tig * 2);
    aq[1] = *(const u32*)(qp + (gid + 8) * 16 + tig * 2);
    aq[2] = *(const u32*)(qp + gid * 16 + tig * 2 + 8);
    aq[3] = *(const u32*)(qp + (gid + 8) * 16 + tig * 2 + 8);
    __syncthreads();

    float4 o0 = make_float4(0.f, 0.f, 0.f, 0.f);
    float4 o1 = make_float4(0.f, 0.f, 0.f, 0.f);
    u64 l2a = 0ull, l2b = 0ull;

    const u32* kw = (const u32*)Ks;
    const u32* vw = (const u32*)Vt;

#pragma unroll 2
    for (int n0 = 0; n0 < NPIX; n0 += 16) {
        u32 kb00 = kw[(n0 + gid) * 12 + tig];
        u32 kb01 = kw[(n0 + gid) * 12 + tig + 4];
        u32 kb10 = kw[(n0 + 8 + gid) * 12 + tig];
        u32 kb11 = kw[(n0 + 8 + gid) * 12 + tig + 4];
        float4 s0 = make_float4(0.f, 0.f, 0.f, 0.f);
        float4 s1 = make_float4(0.f, 0.f, 0.f, 0.f);
        mma16816(s0, aq, kb00, kb01);
        mma16816(s1, aq, kb10, kb11);

        u64 e0 = exp_dual(pack2(s0.x, s0.y));
        u64 e1 = exp_dual(pack2(s0.z, s0.w));
        u64 e2 = exp_dual(pack2(s1.x, s1.y));
        u64 e3 = exp_dual(pack2(s1.z, s1.w));
        l2a = fma2(e0, ONE, l2a); l2a = fma2(e2, ONE, l2a);
        l2b = fma2(e1, ONE, l2b); l2b = fma2(e3, ONE, l2b);

        float2 f0 = unpack2(e0), f1 = unpack2(e1), f2 = unpack2(e2), f3 = unpack2(e3);
        __half2 h0 = __floats2half2_rn(f0.x, f0.y);
        __half2 h1 = __floats2half2_rn(f1.x, f1.y);
        __half2 h2 = __floats2half2_rn(f2.x, f2.y);
        __half2 h3 = __floats2half2_rn(f3.x, f3.y);
        float2 r0 = __half22float2(h0), r1 = __half22float2(h1);
        float2 r2 = __half22float2(h2), r3 = __half22float2(h3);
        u32 ph[4] = {h2u(h0), h2u(h1), h2u(h2), h2u(h3)};
        u32 pl[4] = {h2u(__floats2half2_rn(f0.x - r0.x, f0.y - r0.y)),
                     h2u(__floats2half2_rn(f1.x - r1.x, f1.y - r1.y)),
                     h2u(__floats2half2_rn(f2.x - r2.x, f2.y - r2.y)),
                     h2u(__floats2half2_rn(f3.x - r3.x, f3.y - r3.y))};

        u32 vb00 = vw[gid * 516 + (n0 >> 1) + tig];
        u32 vb01 = vw[gid * 516 + (n0 >> 1) + tig + 4];
        u32 vb10 = vw[(gid + 8) * 516 + (n0 >> 1) + tig];
        u32 vb11 = vw[(gid + 8) * 516 + (n0 >> 1) + tig + 4];

        mma16816(o0, ph, vb00, vb01);
        mma16816(o0, pl, vb00, vb01);
        mma16816(o1, ph, vb10, vb11);
        mma16816(o1, pl, vb10, vb11);
    }

    float2 lA = unpack2(l2a), lB = unpack2(l2b);
    float lr0 = lA.x + lA.y;
    float lr8 = lB.x + lB.y;
    lr0 += __shfl_xor_sync(0xFFFFFFFFu, lr0, 1);
    lr0 += __shfl_xor_sync(0xFFFFFFFFu, lr0, 2);
    lr8 += __shfl_xor_sync(0xFFFFFFFFu, lr8, 1);
    lr8 += __shfl_xor_sync(0xFFFFFFFFu, lr8, 2);
    float i0 = 1.0f / lr0, i8 = 1.0f / lr8;

    const int b = bh >> 3, h = bh & 7;
    float* ob = g_attn + b * (128 * NPIX) + h * (16 * NPIX);
    const int seq0 = qb * 128 + w * 16 + gid;
    const int d0 = tig * 2;
    ob[(d0 + 0) * NPIX + seq0]     = o0.x * i0;
    ob[(d0 + 1) * NPIX + seq0]     = o0.y * i0;
    ob[(d0 + 0) * NPIX + seq0 + 8] = o0.z * i8;
    ob[(d0 + 1) * NPIX + seq0 + 8] = o0.w * i8;
    ob[(d0 + 8) * NPIX + seq0]     = o1.x * i0;
    ob[(d0 + 9) * NPIX + seq0]     = o1.y * i0;
    ob[(d0 + 8) * NPIX + seq0 + 8] = o1.z * i8;
    ob[(d0 + 9) * NPIX + seq0 + 8] = o1.w * i8;
}

// ---------------- kernel 3: attn output projection (unchanged, FFMA2) ------
__global__ __launch_bounds__(256, 2) void k_attnproj(
    const float* __restrict__ w_attn, const float* __restrict__ b_attn,
    float* __restrict__ out)
{
    __shared__ float As[16][128];
    __shared__ float Bs[16][128];
    const int b  = blockIdx.z;
    const int n0 = blockIdx.x * 128;
    const int tid = threadIdx.x;
    const int tx = tid & 15;
    const int ty = tid >> 4;
    const float* Bsrc = g_attn + b * (128 * NPIX);

    const int a_ml0 = tid & 127, a_kq0 = (tid >> 7);
    const int b_kl0 = tid >> 5, b_nl0 = (tid & 31) * 4;

    float4 ar[2], br[2];
    ar[0] = *(const float4*)&w_attn[a_ml0 * 128 + a_kq0 * 4];
    ar[1] = *(const float4*)&w_attn[a_ml0 * 128 + (a_kq0 + 2) * 4];
    br[0] = *(const float4*)&Bsrc[b_kl0 * NPIX + n0 + b_nl0];
    br[1] = *(const float4*)&Bsrc[(b_kl0 + 8) * NPIX + n0 + b_nl0];

    u64 acc[8][4];
#pragma unroll
    for (int i = 0; i < 8; ++i)
#pragma unroll
        for (int j = 0; j < 4; ++j) acc[i][j] = 0ull;

    for (int c = 0; c < 8; ++c) {
        __syncthreads();
#pragma unroll
        for (int r = 0; r < 2; ++r) {
            int kq = a_kq0 + r * 2;
            As[kq * 4 + 0][a_ml0] = ((float*)&ar[r])[0];
            As[kq * 4 + 1][a_ml0] = ((float*)&ar[r])[1];
            As[kq * 4 + 2][a_ml0] = ((float*)&ar[r])[2];
            As[kq * 4 + 3][a_ml0] = ((float*)&ar[r])[3];
        }
        *(float4*)&Bs[b_kl0][b_nl0]     = br[0];
        *(float4*)&Bs[b_kl0 + 8][b_nl0] = br[1];
        __syncthreads();
        if (c < 7) {
            int k0 = (c + 1) * 16;
            ar[0] = *(const float4*)&w_attn[a_ml0 * 128 + k0 + a_kq0 * 4];
            ar[1] = *(const float4*)&w_attn[a_ml0 * 128 + k0 + (a_kq0 + 2) * 4];
            br[0] = *(const float4*)&Bsrc[(k0 + b_kl0) * NPIX + n0 + b_nl0];
            br[1] = *(const float4*)&Bsrc[(k0 + b_kl0 + 8) * NPIX + n0 + b_nl0];
        }
#pragma unroll
        for (int kk = 0; kk < 16; ++kk) {
            float4 a0 = *(const float4*)&As[kk][ty * 8];
            float4 a1 = *(const float4*)&As[kk][ty * 8 + 4];
            ulonglong2 b01 = *(const ulonglong2*)&Bs[kk][tx * 8];
            ulonglong2 b23 = *(const ulonglong2*)&Bs[kk][tx * 8 + 4];
            u64 bp[4] = {b01.x, b01.y, b23.x, b23.y};
            float am[8] = {a0.x, a0.y, a0.z, a0.w, a1.x, a1.y, a1.z, a1.w};
#pragma unroll
            for (int i = 0; i < 8; ++i) {
                u64 ad = pack2(am[i], am[i]);
#pragma unroll
                for (int j = 0; j < 4; ++j)
                    acc[i][j] = fma2(ad, bp[j], acc[i][j]);
            }
        }
    }

#pragma unroll
    for (int i = 0; i < 8; ++i) {
        int m = ty * 8 + i;
        float bias = b_attn[m];
        float v[8];
#pragma unroll
        for (int j = 0; j < 4; ++j) {
            float2 t = unpack2(acc[i][j]);
            v[j * 2 + 0] = t.x + bias;
            v[j * 2 + 1] = t.y + bias;
        }
        float* dst = out + b * 262144 + (128 + m) * NPIX + n0 + tx * 8;
        *(float4*)dst       = make_float4(v[0], v[1], v[2], v[3]);
        *(float4*)(dst + 4) = make_float4(v[4], v[5], v[6], v[7]);
    }
}

// ---------------- launch ----------------------------------------------------
extern "C" void kernel_launch(void* const* d_in, const int* in_sizes, int n_in,
                              void* d_out, int out_size)
{
    const float* x      = (const float*)d_in[0];
    const float* w_qkv  = (const float*)d_in[1];
    const float* b_qkv  = (const float*)d_in[2];
    const float* w_attn = (const float*)d_in[3];
    const float* b_attn = (const float*)d_in[4];
    const float* w_out  = (const float*)d_in[5];
    const float* b_out  = (const float*)d_in[6];
    float* out = (float*)d_out;

    k_cvt_w<<<512, 64>>>(w_qkv, w_out);
    dim3 gc(64, 32);
    k_cvt_x<<<gc, 256>>>(x);

    dim3 g1(8, 4, 32);                 // n-tiles(128), m-tiles(q/k/v/conv), batch
    k_proj<<<g1, 256>>>(b_qkv, b_out, out);

    const int smem_attn = (1024 * KROW + 16 * VROW) * (int)sizeof(__half); // 82176
    cudaFuncSetAttribute(k_attn, cudaFuncAttributeMaxDynamicSharedMemorySize,
                         smem_attn);
    dim3 g2(8, 256);                   // q-blocks x (b,h)
    k_attn<<<g2, 256, smem_attn>>>();

    dim3 g3(8, 1, 32);
    k_attnproj<<<g3, 256>>>(w_attn, b_attn, out);
}

// round 12
// speedup vs baseline: 1.6372x; 1.1313x over previous
#include <cuda_runtime.h>
#include <cuda_fp16.h>

// ---------------- problem constants ----------------
// B=32, CIN=256, H=W=32 (N=1024), DK=DV=128, HEADS=8, DKH=DVH=16, OUT=256
#define NB    32
#define NPIX  1024
#define NCIN  256

typedef unsigned long long u64;
typedef unsigned int u32;

// ---------------- scratch (static device mem; no allocations allowed) ------
__device__ __half g_qh[32 * 8 * 1024 * 16];   // [bh][n][16]  (pre-scaled 0.25)
__device__ __half g_kh[32 * 8 * 1024 * 16];   // [bh][n][16]
__device__ __half g_vt[32 * 8 * 16 * 1024];   // [bh][d][n]   (transposed)
__device__ float  g_attn[32 * 128 * 1024];    // [b][dv][n]
// pre-converted hi/lo fp16 operands (chunk-major for coalesced staging)
__device__ __half g_wh[4 * 16 * 128 * 16];    // [mt][cs][128m][16k]
__device__ __half g_wl[4 * 16 * 128 * 16];
__device__ __half g_xh[32 * 16 * 1024 * 16];  // [b][cs][1024n][16k]
__device__ __half g_xl[32 * 16 * 1024 * 16];

// ---------------- packed f32x2 helpers -------------------------------------
__device__ __forceinline__ u64 fma2(u64 a, u64 b, u64 c) {
    u64 d;
    asm("fma.rn.f32x2 %0, %1, %2, %3;" : "=l"(d) : "l"(a), "l"(b), "l"(c));
    return d;
}
__device__ __forceinline__ u64 pack2(float lo, float hi) {
    u64 d;
    asm("mov.b64 %0, {%1, %2};" : "=l"(d) : "f"(lo), "f"(hi));
    return d;
}
__device__ __forceinline__ float2 unpack2(u64 v) {
    float2 r;
    asm("mov.b64 {%0, %1}, %2;" : "=f"(r.x), "=f"(r.y) : "l"(v));
    return r;
}
__device__ __forceinline__ void split64(u64 v, u32& lo, u32& hi) {
    asm("mov.b64 {%0, %1}, %2;" : "=r"(lo), "=r"(hi) : "l"(v));
}
__device__ __forceinline__ u64 join64(u32 lo, u32 hi) {
    u64 d;
    asm("mov.b64 %0, {%1, %2};" : "=l"(d) : "r"(lo), "r"(hi));
    return d;
}
__device__ __forceinline__ u64 make2(float v) { return pack2(v, v); }
__device__ __forceinline__ u32 h2u(__half2 h) {
    union { __half2 h; u32 u; } c; c.h = h; return c.u;
}

// ---------------- dual packed exp (magic round + deg-4 poly, FMA pipe) -----
__device__ __forceinline__ u64 exp_dual(u64 s2) {
    const u64 ONE   = make2(1.0f);
    const u64 NEG1  = make2(-1.0f);
    const u64 L2E   = make2(1.4426950408889634f);
    const u64 MAGIC = make2(12582912.0f);            // 2^23 + 2^22
    const u64 C4 = make2(9.6181291e-3f);
    const u64 C3 = make2(5.5504109e-2f);
    const u64 C2 = make2(2.4022651e-1f);
    const u64 C1 = make2(6.9314718e-1f);
    u64 y = fma2(s2, L2E, 0ull);
    u64 r = fma2(y, ONE, MAGIC);
    u64 t = fma2(MAGIC, NEG1, r);
    u64 f = fma2(t, NEG1, y);
    u64 p = fma2(C4, f, C3);
    p = fma2(p, f, C2);
    p = fma2(p, f, C1);
    p = fma2(p, f, ONE);
    u32 rl, rh;
    split64(r, rl, rh);
    u32 sl = (rl + 0xB4C0007Fu) << 23;
    u32 sh = (rh + 0xB4C0007Fu) << 23;
    return fma2(p, join64(sl, sh), 0ull);
}

// ---------------- mma.sync m16n8k16 fp16 -> fp32 ---------------------------
__device__ __forceinline__ void mma16816(float4& c, const u32* a, u32 b0, u32 b1) {
    asm volatile(
        "mma.sync.aligned.m16n8k16.row.col.f32.f16.f16.f32 "
        "{%0,%1,%2,%3}, {%4,%5,%6,%7}, {%8,%9}, {%0,%1,%2,%3};"
        : "+f"(c.x), "+f"(c.y), "+f"(c.z), "+f"(c.w)
        : "r"(a[0]), "r"(a[1]), "r"(a[2]), "r"(a[3]), "r"(b0), "r"(b1));
}

__device__ __forceinline__ void hsplit(float v, __half& hi, __half& lo) {
    hi = __float2half_rn(v);
    lo = __float2half_rn(v - __half2float(hi));
}

// ---------------- pre-pass: convert weights to hi/lo fp16 chunk-major ------
__global__ void k_cvt_w(const float* __restrict__ w_qkv,
                        const float* __restrict__ w_out)
{
    const int m = blockIdx.x;
    const int k0 = threadIdx.x * 4;
    const float* src = (m < 384) ? &w_qkv[m * NCIN + k0]
                                 : &w_out[(m - 384) * NCIN + k0];
    const float sc = (m < 128) ? 0.25f : 1.0f;
    float4 v = *(const float4*)src;
    __half h[4], l[4];
    hsplit(v.x * sc, h[0], l[0]);
    hsplit(v.y * sc, h[1], l[1]);
    hsplit(v.z * sc, h[2], l[2]);
    hsplit(v.w * sc, h[3], l[3]);
    const int mt = m >> 7, ml = m & 127, cs = k0 >> 4, ko = k0 & 15;
    const int dst = ((mt * 16 + cs) * 128 + ml) * 16 + ko;
    *(uint2*)&g_wh[dst] = *(uint2*)h;
    *(uint2*)&g_wl[dst] = *(uint2*)l;
}

// ---------------- pre-pass: transpose+convert x to hi/lo chunk-major -------
__global__ __launch_bounds__(256) void k_cvt_x(const float* __restrict__ x)
{
    __shared__ float tile[16][260];
    const int cc = blockIdx.x >> 2;          // k-chunk 0..15
    const int ng = blockIdx.x & 3;           // n-group (256 cols)
    const int b  = blockIdx.y;
    const int tid = threadIdx.x;
#pragma unroll
    for (int i = 0; i < 4; ++i) {
        int idx = tid + i * 256;             // 0..1023
        int r = idx >> 6, c4 = (idx & 63) * 4;
        float4 v = *(const float4*)&x[b * (NCIN * NPIX) + (cc * 16 + r) * NPIX
                                      + ng * 256 + c4];
        tile[r][c4 + 0] = v.x; tile[r][c4 + 1] = v.y;
        tile[r][c4 + 2] = v.z; tile[r][c4 + 3] = v.w;
    }
    __syncthreads();
    __half h[16], l[16];
#pragma unroll
    for (int k = 0; k < 16; ++k) hsplit(tile[k][tid], h[k], l[k]);
    const int dst = ((b * 16 + cc) * 1024 + ng * 256 + tid) * 16;
    *(uint4*)&g_xh[dst]     = *(uint4*)&h[0];
    *(uint4*)&g_xh[dst + 8] = *(uint4*)&h[8];
    *(uint4*)&g_xl[dst]     = *(uint4*)&l[0];
    *(uint4*)&g_xl[dst + 8] = *(uint4*)&l[8];
}

// ---------------- kernel 1: tensor-core fused projection (R10-verified) ----
#define SSTR 132
__global__ __launch_bounds__(256, 2) void k_proj(
    const float* __restrict__ b_qkv, const float* __restrict__ b_out,
    float* __restrict__ out)
{
    __shared__ __align__(16) char smraw[24576];
    __half* sAh = (__half*)smraw;            // [128 m][24]
    __half* sAl = (__half*)smraw + 3072;
    __half* sBh = (__half*)smraw + 6144;     // [128 n][24]
    __half* sBl = (__half*)smraw + 9216;
    float*  S   = (float*)smraw;             // epilogue alias [32][SSTR]

    const int b  = blockIdx.z;
    const int mt = blockIdx.y;               // 0=q 1=k 2=v 3=conv
    const int n0 = blockIdx.x * 128;
    const int tid = threadIdx.x;
    const int w    = tid >> 5;
    const int lane = tid & 31;
    const int gid = lane >> 2, tig = lane & 3;
    const int wm = w & 3;                    // m-quarter (32 rows)
    const int wn = w >> 2;                   // n-half (64 cols)

    const int sm_row = tid >> 1;             // m or n row 0..127
    const int sm_hp  = tid & 1;              // which 8-half group of chunk

    const __half* wsrch = g_wh + (mt * 16) * 128 * 16;
    const __half* wsrcl = g_wl + (mt * 16) * 128 * 16;
    const __half* xsrch = g_xh + ((u64)b * 16) * 1024 * 16;
    const __half* xsrcl = g_xl + ((u64)b * 16) * 1024 * 16;
    const int aoff = sm_row * 16 + sm_hp * 8;
    const int boff = (n0 + sm_row) * 16 + sm_hp * 8;

    uint4 pah, pal, pbh, pbl;
    pah = *(const uint4*)&wsrch[aoff];
    pal = *(const uint4*)&wsrcl[aoff];
    pbh = *(const uint4*)&xsrch[boff];
    pbl = *(const uint4*)&xsrcl[boff];

    float4 c[2][8];
#pragma unroll
    for (int t = 0; t < 2; ++t)
#pragma unroll
        for (int nb = 0; nb < 8; ++nb) c[t][nb] = make_float4(0.f, 0.f, 0.f, 0.f);

    for (int cs = 0; cs < 16; ++cs) {
        __syncthreads();
        *(uint4*)&sAh[sm_row * 24 + sm_hp * 8] = pah;
        *(uint4*)&sAl[sm_row * 24 + sm_hp * 8] = pal;
        *(uint4*)&sBh[sm_row * 24 + sm_hp * 8] = pbh;
        *(uint4*)&sBl[sm_row * 24 + sm_hp * 8] = pbl;
        __syncthreads();
        if (cs < 15) {
            const int anext = (cs + 1) * 128 * 16 + aoff;
            const int bnext = (cs + 1) * 1024 * 16 + boff;
            pah = *(const uint4*)&wsrch[anext];
            pal = *(const uint4*)&wsrcl[anext];
            pbh = *(const uint4*)&xsrch[bnext];
            pbl = *(const uint4*)&xsrcl[bnext];
        }

        const u32* Ahw = (const u32*)sAh;
        const u32* Alw = (const u32*)sAl;
        const u32* Bhw = (const u32*)sBh;
        const u32* Blw = (const u32*)sBl;

        u32 ah[2][4], al[2][4];
#pragma unroll
        for (int t = 0; t < 2; ++t) {
            int r0 = wm * 32 + t * 16 + gid;
            ah[t][0] = Ahw[r0 * 12 + tig];
            ah[t][1] = Ahw[(r0 + 8) * 12 + tig];
            ah[t][2] = Ahw[r0 * 12 + tig + 4];
            ah[t][3] = Ahw[(r0 + 8) * 12 + tig + 4];
            al[t][0] = Alw[r0 * 12 + tig];
            al[t][1] = Alw[(r0 + 8) * 12 + tig];
            al[t][2] = Alw[r0 * 12 + tig + 4];
            al[t][3] = Alw[(r0 + 8) * 12 + tig + 4];
        }
        u32 bf[8][2];
#pragma unroll
        for (int nb = 0; nb < 8; ++nb) {
            int n = wn * 64 + nb * 8 + gid;
            bf[nb][0] = Bhw[n * 12 + tig];
            bf[nb][1] = Bhw[n * 12 + tig + 4];
        }
#pragma unroll
        for (int nb = 0; nb < 8; ++nb) {
            mma16816(c[0][nb], ah[0], bf[nb][0], bf[nb][1]);
            mma16816(c[1][nb], ah[1], bf[nb][0], bf[nb][1]);
            mma16816(c[0][nb], al[0], bf[nb][0], bf[nb][1]);
            mma16816(c[1][nb], al[1], bf[nb][0], bf[nb][1]);
        }
#pragma unroll
        for (int nb = 0; nb < 8; ++nb) {
            int n = wn * 64 + nb * 8 + gid;
            bf[nb][0] = Blw[n * 12 + tig];
            bf[nb][1] = Blw[n * 12 + tig + 4];
        }
#pragma unroll
        for (int nb = 0; nb < 8; ++nb) {
            mma16816(c[0][nb], ah[0], bf[nb][0], bf[nb][1]);
            mma16816(c[1][nb], ah[1], bf[nb][0], bf[nb][1]);
        }
    }

    const float wscale = (mt == 0) ? 0.25f : 1.0f;
    float bias[2][2];
#pragma unroll
    for (int t = 0; t < 2; ++t) {
        int m = wm * 32 + t * 16 + gid;
        if (mt < 3) {
            bias[t][0] = b_qkv[mt * 128 + m] * wscale;
            bias[t][1] = b_qkv[mt * 128 + m + 8] * wscale;
        } else {
            bias[t][0] = b_out[m];
            bias[t][1] = b_out[m + 8];
        }
    }
#pragma unroll
    for (int t = 0; t < 2; ++t)
#pragma unroll
        for (int nb = 0; nb < 8; ++nb) {
            c[t][nb].x += bias[t][0]; c[t][nb].y += bias[t][0];
            c[t][nb].z += bias[t][1]; c[t][nb].w += bias[t][1];
        }

    for (int mc = 0; mc < 4; ++mc) {
        __syncthreads();
        if (wm == mc) {
#pragma unroll
            for (int t = 0; t < 2; ++t)
#pragma unroll
                for (int nb = 0; nb < 8; ++nb) {
                    int col = wn * 64 + nb * 8 + tig * 2;
                    int r0 = t * 16 + gid;
                    *(float2*)&S[r0 * SSTR + col]       = make_float2(c[t][nb].x, c[t][nb].y);
                    *(float2*)&S[(r0 + 8) * SSTR + col] = make_float2(c[t][nb].z, c[t][nb].w);
                }
        }
        __syncthreads();

        if (mt == 3) {
#pragma unroll
            for (int t = 0; t < 4; ++t) {
                int idx = tid + t * 256;
                int nq = idx & 31, row = idx >> 5;
                float4 v = *(const float4*)&S[row * SSTR + nq * 4];
                *(float4*)&out[b * 262144 + (mc * 32 + row) * NPIX + n0 + nq * 4] = v;
            }
        } else if (mt == 2) {
#pragma unroll
            for (int t = 0; t < 2; ++t) {
                int idx = tid + t * 256;
                int noct = idx & 15, row = idx >> 4;
                const float* sp = &S[row * SSTR + noct * 8];
                uint4 u;
                u.x = h2u(__floats2half2_rn(sp[0], sp[1]));
                u.y = h2u(__floats2half2_rn(sp[2], sp[3]));
                u.z = h2u(__floats2half2_rn(sp[4], sp[5]));
                u.w = h2u(__floats2half2_rn(sp[6], sp[7]));
                int h = mc * 2 + (row >> 4);
                int d = row & 15;
                *(uint4*)&g_vt[(((b * 8 + h) * 16 + d) << 10) + n0 + noct * 8] = u;
            }
        } else {
            __half* g = (mt == 0) ? g_qh : g_kh;
#pragma unroll
            for (int t = 0; t < 2; ++t) {
                int idx = tid + t * 256;
                int n = idx & 127;
                int rest = idx >> 7;
                int hsel = rest >> 1, dh = rest & 1;
                int rb = hsel * 16 + dh * 8;
                uint4 u;
                u.x = h2u(__floats2half2_rn(S[(rb + 0) * SSTR + n], S[(rb + 1) * SSTR + n]));
                u.y = h2u(__floats2half2_rn(S[(rb + 2) * SSTR + n], S[(rb + 3) * SSTR + n]));
                u.z = h2u(__floats2half2_rn(S[(rb + 4) * SSTR + n], S[(rb + 5) * SSTR + n]));
                u.w = h2u(__floats2half2_rn(S[(rb + 6) * SSTR + n], S[(rb + 7) * SSTR + n]));
                int bh = b * 8 + mc * 2 + hsel;
                *(uint4*)&g[((u64)bh << 14) + (u64)(n0 + n) * 16 + dh * 8] = u;
            }
        }
    }
}

// ---------------- kernel 2: tensor-core attention (P hi-only, occ 3) -------
#define KROW 24       // halves per Ks row (12 words, conflict-free frags)
#define VROW 1032     // halves per Vt row (516 words)
__global__ __launch_bounds__(256, 3) void k_attn()
{
    extern __shared__ __half sm[];
    __half* Ks = sm;                    // [1024][KROW]
    __half* Vt = sm + 1024 * KROW;      // [16][VROW]
    const int qb  = blockIdx.x;
    const int bh  = blockIdx.y;
    const int tid = threadIdx.x;
    const int w   = tid >> 5;
    const int lane = tid & 31;
    const int gid = lane >> 2, tig = lane & 3;
    const u64 ONE = make2(1.0f);

    const uint4* ksrc = (const uint4*)(g_kh + ((u64)bh << 14));
    const uint4* vsrc = (const uint4*)(g_vt + ((u64)bh << 14));
#pragma unroll
    for (int j = 0; j < 8; ++j) {
        int idx = tid + j * 256;
        int seq = idx >> 1, hp = idx & 1;
        *(uint4*)&Ks[seq * KROW + hp * 8] = ksrc[idx];
    }
#pragma unroll
    for (int j = 0; j < 8; ++j) {
        int idx = tid + j * 256;
        int row = idx >> 7, off = (idx & 127) * 8;
        *(uint4*)&Vt[row * VROW + off] = vsrc[idx];
    }

    const __half* qp = g_qh + ((u64)bh << 14) + (qb * 128 + w * 16) * 16;
    u32 aq[4];
    aq[0] = *(const u32*)(qp + gid * 16 + tig * 2);
    aq[1] = *(const u32*)(qp + (gid + 8) * 16 + tig * 2);
    aq[2] = *(const u32*)(qp + gid * 16 + tig * 2 + 8);
    aq[3] = *(const u32*)(qp + (gid + 8) * 16 + tig * 2 + 8);
    __syncthreads();

    float4 o0 = make_float4(0.f, 0.f, 0.f, 0.f);
    float4 o1 = make_float4(0.f, 0.f, 0.f, 0.f);
    u64 l2a = 0ull, l2b = 0ull;

    const u32* kw = (const u32*)Ks;
    const u32* vw = (const u32*)Vt;

#pragma unroll 2
    for (int n0 = 0; n0 < NPIX; n0 += 16) {
        u32 kb00 = kw[(n0 + gid) * 12 + tig];
        u32 kb01 = kw[(n0 + gid) * 12 + tig + 4];
        u32 kb10 = kw[(n0 + 8 + gid) * 12 + tig];
        u32 kb11 = kw[(n0 + 8 + gid) * 12 + tig + 4];
        float4 s0 = make_float4(0.f, 0.f, 0.f, 0.f);
        float4 s1 = make_float4(0.f, 0.f, 0.f, 0.f);
        mma16816(s0, aq, kb00, kb01);
        mma16816(s1, aq, kb10, kb11);

        u64 e0 = exp_dual(pack2(s0.x, s0.y));
        u64 e1 = exp_dual(pack2(s0.z, s0.w));
        u64 e2 = exp_dual(pack2(s1.x, s1.y));
        u64 e3 = exp_dual(pack2(s1.z, s1.w));
        l2a = fma2(e0, ONE, l2a); l2a = fma2(e2, ONE, l2a);
        l2b = fma2(e1, ONE, l2b); l2b = fma2(e3, ONE, l2b);

        // P fragments: hi only (fp16-rn error ~2.4e-4/weight -> ~1e-4 output)
        float2 f0 = unpack2(e0), f1 = unpack2(e1), f2 = unpack2(e2), f3 = unpack2(e3);
        u32 ph[4] = {h2u(__floats2half2_rn(f0.x, f0.y)),
                     h2u(__floats2half2_rn(f1.x, f1.y)),
                     h2u(__floats2half2_rn(f2.x, f2.y)),
                     h2u(__floats2half2_rn(f3.x, f3.y))};

        u32 vb00 = vw[gid * 516 + (n0 >> 1) + tig];
        u32 vb01 = vw[gid * 516 + (n0 >> 1) + tig + 4];
        u32 vb10 = vw[(gid + 8) * 516 + (n0 >> 1) + tig];
        u32 vb11 = vw[(gid + 8) * 516 + (n0 >> 1) + tig + 4];

        mma16816(o0, ph, vb00, vb01);
        mma16816(o1, ph, vb10, vb11);
    }

    float2 lA = unpack2(l2a), lB = unpack2(l2b);
    float lr0 = lA.x + lA.y;
    float lr8 = lB.x + lB.y;
    lr0 += __shfl_xor_sync(0xFFFFFFFFu, lr0, 1);
    lr0 += __shfl_xor_sync(0xFFFFFFFFu, lr0, 2);
    lr8 += __shfl_xor_sync(0xFFFFFFFFu, lr8, 1);
    lr8 += __shfl_xor_sync(0xFFFFFFFFu, lr8, 2);
    float i0 = 1.0f / lr0, i8 = 1.0f / lr8;

    const int b = bh >> 3, h = bh & 7;
    float* ob = g_attn + b * (128 * NPIX) + h * (16 * NPIX);
    const int seq0 = qb * 128 + w * 16 + gid;
    const int d0 = tig * 2;
    ob[(d0 + 0) * NPIX + seq0]     = o0.x * i0;
    ob[(d0 + 1) * NPIX + seq0]     = o0.y * i0;
    ob[(d0 + 0) * NPIX + seq0 + 8] = o0.z * i8;
    ob[(d0 + 1) * NPIX + seq0 + 8] = o0.w * i8;
    ob[(d0 + 8) * NPIX + seq0]     = o1.x * i0;
    ob[(d0 + 9) * NPIX + seq0]     = o1.y * i0;
    ob[(d0 + 8) * NPIX + seq0 + 8] = o1.z * i8;
    ob[(d0 + 9) * NPIX + seq0 + 8] = o1.w * i8;
}

// ---------------- kernel 3: attn output projection (unchanged, FFMA2) ------
__global__ __launch_bounds__(256, 2) void k_attnproj(
    const float* __restrict__ w_attn, const float* __restrict__ b_attn,
    float* __restrict__ out)
{
    __shared__ float As[16][128];
    __shared__ float Bs[16][128];
    const int b  = blockIdx.z;
    const int n0 = blockIdx.x * 128;
    const int tid = threadIdx.x;
    const int tx = tid & 15;
    const int ty = tid >> 4;
    const float* Bsrc = g_attn + b * (128 * NPIX);

    const int a_ml0 = tid & 127, a_kq0 = (tid >> 7);
    const int b_kl0 = tid >> 5, b_nl0 = (tid & 31) * 4;

    float4 ar[2], br[2];
    ar[0] = *(const float4*)&w_attn[a_ml0 * 128 + a_kq0 * 4];
    ar[1] = *(const float4*)&w_attn[a_ml0 * 128 + (a_kq0 + 2) * 4];
    br[0] = *(const float4*)&Bsrc[b_kl0 * NPIX + n0 + b_nl0];
    br[1] = *(const float4*)&Bsrc[(b_kl0 + 8) * NPIX + n0 + b_nl0];

    u64 acc[8][4];
#pragma unroll
    for (int i = 0; i < 8; ++i)
#pragma unroll
        for (int j = 0; j < 4; ++j) acc[i][j] = 0ull;

    for (int c = 0; c < 8; ++c) {
        __syncthreads();
#pragma unroll
        for (int r = 0; r < 2; ++r) {
            int kq = a_kq0 + r * 2;
            As[kq * 4 + 0][a_ml0] = ((float*)&ar[r])[0];
            As[kq * 4 + 1][a_ml0] = ((float*)&ar[r])[1];
            As[kq * 4 + 2][a_ml0] = ((float*)&ar[r])[2];
            As[kq * 4 + 3][a_ml0] = ((float*)&ar[r])[3];
        }
        *(float4*)&Bs[b_kl0][b_nl0]     = br[0];
        *(float4*)&Bs[b_kl0 + 8][b_nl0] = br[1];
        __syncthreads();
        if (c < 7) {
            int k0 = (c + 1) * 16;
            ar[0] = *(const float4*)&w_attn[a_ml0 * 128 + k0 + a_kq0 * 4];
            ar[1] = *(const float4*)&w_attn[a_ml0 * 128 + k0 + (a_kq0 + 2) * 4];
            br[0] = *(const float4*)&Bsrc[(k0 + b_kl0) * NPIX + n0 + b_nl0];
            br[1] = *(const float4*)&Bsrc[(k0 + b_kl0 + 8) * NPIX + n0 + b_nl0];
        }
#pragma unroll
        for (int kk = 0; kk < 16; ++kk) {
            float4 a0 = *(const float4*)&As[kk][ty * 8];
            float4 a1 = *(const float4*)&As[kk][ty * 8 + 4];
            ulonglong2 b01 = *(const ulonglong2*)&Bs[kk][tx * 8];
            ulonglong2 b23 = *(const ulonglong2*)&Bs[kk][tx * 8 + 4];
            u64 bp[4] = {b01.x, b01.y, b23.x, b23.y};
            float am[8] = {a0.x, a0.y, a0.z, a0.w, a1.x, a1.y, a1.z, a1.w};
#pragma unroll
            for (int i = 0; i < 8; ++i) {
                u64 ad = pack2(am[i], am[i]);
#pragma unroll
                for (int j = 0; j < 4; ++j)
                    acc[i][j] = fma2(ad, bp[j], acc[i][j]);
            }
        }
    }

#pragma unroll
    for (int i = 0; i < 8; ++i) {
        int m = ty * 8 + i;
        float bias = b_attn[m];
        float v[8];
#pragma unroll
        for (int j = 0; j < 4; ++j) {
            float2 t = unpack2(acc[i][j]);
            v[j * 2 + 0] = t.x + bias;
            v[j * 2 + 1] = t.y + bias;
        }
        float* dst = out + b * 262144 + (128 + m) * NPIX + n0 + tx * 8;
        *(float4*)dst       = make_float4(v[0], v[1], v[2], v[3]);
        *(float4*)(dst + 4) = make_float4(v[4], v[5], v[6], v[7]);
    }
}

// ---------------- launch ----------------------------------------------------
extern "C" void kernel_launch(void* const* d_in, const int* in_sizes, int n_in,
                              void* d_out, int out_size)
{
    const float* x      = (const float*)d_in[0];
    const float* w_qkv  = (const float*)d_in[1];
    const float* b_qkv  = (const float*)d_in[2];
    const float* w_attn = (const float*)d_in[3];
    const float* b_attn = (const float*)d_in[4];
    const float* w_out  = (const float*)d_in[5];
    const float* b_out  = (const float*)d_in[6];
    float* out = (float*)d_out;

    k_cvt_w<<<512, 64>>>(w_qkv, w_out);
    dim3 gc(64, 32);
    k_cvt_x<<<gc, 256>>>(x);

    dim3 g1(8, 4, 32);                 // n-tiles(128), m-tiles(q/k/v/conv), batch
    k_proj<<<g1, 256>>>(b_qkv, b_out, out);

    const int smem_attn = (1024 * KROW + 16 * VROW) * (int)sizeof(__half); // 82176
    cudaFuncSetAttribute(k_attn, cudaFuncAttributeMaxDynamicSharedMemorySize,
                         smem_attn);
    dim3 g2(8, 256);                   // q-blocks x (b,h)
    k_attn<<<g2, 256, smem_attn>>>();

    dim3 g3(8, 1, 32);
    k_attnproj<<<g3, 256>>>(w_attn, b_attn, out);
}

// round 13
// speedup vs baseline: 1.7018x; 1.0395x over previous
#include <cuda_runtime.h>
#include <cuda_fp16.h>

// ---------------- problem constants ----------------
// B=32, CIN=256, H=W=32 (N=1024), DK=DV=128, HEADS=8, DKH=DVH=16, OUT=256
#define NB    32
#define NPIX  1024
#define NCIN  256

typedef unsigned long long u64;
typedef unsigned int u32;

// ---------------- scratch (static device mem; no allocations allowed) ------
__device__ __half g_qh[32 * 8 * 1024 * 16];   // [bh][n][16]  (pre-scaled 0.25)
__device__ __half g_kh[32 * 8 * 1024 * 16];   // [bh][n][16]
__device__ __half g_vt[32 * 8 * 16 * 1024];   // [bh][d][n]   (transposed)
__device__ float  g_attn[32 * 128 * 1024];    // [b][dv][n]
// pre-converted hi/lo fp16 operands (chunk-major for coalesced staging)
__device__ __half g_wh[4 * 16 * 128 * 16];    // [mt][cs][128m][16k]
__device__ __half g_wl[4 * 16 * 128 * 16];
__device__ __half g_xh[32 * 16 * 1024 * 16];  // [b][cs][1024n][16k]
__device__ __half g_xl[32 * 16 * 1024 * 16];

// ---------------- packed f32x2 helpers -------------------------------------
__device__ __forceinline__ u64 fma2(u64 a, u64 b, u64 c) {
    u64 d;
    asm("fma.rn.f32x2 %0, %1, %2, %3;" : "=l"(d) : "l"(a), "l"(b), "l"(c));
    return d;
}
__device__ __forceinline__ u64 pack2(float lo, float hi) {
    u64 d;
    asm("mov.b64 %0, {%1, %2};" : "=l"(d) : "f"(lo), "f"(hi));
    return d;
}
__device__ __forceinline__ float2 unpack2(u64 v) {
    float2 r;
    asm("mov.b64 {%0, %1}, %2;" : "=f"(r.x), "=f"(r.y) : "l"(v));
    return r;
}
__device__ __forceinline__ void split64(u64 v, u32& lo, u32& hi) {
    asm("mov.b64 {%0, %1}, %2;" : "=r"(lo), "=r"(hi) : "l"(v));
}
__device__ __forceinline__ u64 join64(u32 lo, u32 hi) {
    u64 d;
    asm("mov.b64 %0, {%1, %2};" : "=l"(d) : "r"(lo), "r"(hi));
    return d;
}
__device__ __forceinline__ u64 make2(float v) { return pack2(v, v); }
__device__ __forceinline__ u32 h2u(__half2 h) {
    union { __half2 h; u32 u; } c; c.h = h; return c.u;
}

// ---------------- dual packed exp, 7 fma2 + ALU bits-add --------------------
// r = RN(y + MAGIC) holds i in mantissa; MAGIC-r = -i exact; f = y - i.
// Final scale by 2^i via exponent-bits add: bits(p) + (bits(r) << 23).
// (MAGIC low 9 bits are zero, so (r_bits << 23) == i << 23 exactly.)
__device__ __forceinline__ u64 exp_dual(u64 s2) {
    const u64 ONE   = make2(1.0f);
    const u64 NEG1  = make2(-1.0f);
    const u64 L2E   = make2(1.4426950408889634f);
    const u64 MAGIC = make2(12582912.0f);            // 2^23 + 2^22
    const u64 C4 = make2(9.6181291e-3f);
    const u64 C3 = make2(5.5504109e-2f);
    const u64 C2 = make2(2.4022651e-1f);
    const u64 C1 = make2(6.9314718e-1f);
    u64 r  = fma2(s2, L2E, MAGIC);      // y + magic (RN -> i in mantissa)
    u64 mr = fma2(r, NEG1, MAGIC);      // -i (exact)
    u64 f  = fma2(s2, L2E, mr);         // f = y - i in [-0.5, 0.5]
    u64 p  = fma2(C4, f, C3);
    p = fma2(p, f, C2);
    p = fma2(p, f, C1);
    p = fma2(p, f, ONE);                // p ~= 2^f in [0.707, 1.415]
    u32 rl, rh, pl, ph;
    split64(r, rl, rh);
    split64(p, pl, ph);
    return join64(pl + (rl << 23), ph + (rh << 23));   // p * 2^i (bit-exact)
}

// ---------------- mma.sync m16n8k16 fp16 -> fp32 ---------------------------
__device__ __forceinline__ void mma16816(float4& c, const u32* a, u32 b0, u32 b1) {
    asm volatile(
        "mma.sync.aligned.m16n8k16.row.col.f32.f16.f16.f32 "
        "{%0,%1,%2,%3}, {%4,%5,%6,%7}, {%8,%9}, {%0,%1,%2,%3};"
        : "+f"(c.x), "+f"(c.y), "+f"(c.z), "+f"(c.w)
        : "r"(a[0]), "r"(a[1]), "r"(a[2]), "r"(a[3]), "r"(b0), "r"(b1));
}

__device__ __forceinline__ void hsplit(float v, __half& hi, __half& lo) {
    hi = __float2half_rn(v);
    lo = __float2half_rn(v - __half2float(hi));
}

// ---------------- pre-pass: convert weights to hi/lo fp16 chunk-major ------
__global__ void k_cvt_w(const float* __restrict__ w_qkv,
                        const float* __restrict__ w_out)
{
    const int m = blockIdx.x;
    const int k0 = threadIdx.x * 4;
    const float* src = (m < 384) ? &w_qkv[m * NCIN + k0]
                                 : &w_out[(m - 384) * NCIN + k0];
    const float sc = (m < 128) ? 0.25f : 1.0f;
    float4 v = *(const float4*)src;
    __half h[4], l[4];
    hsplit(v.x * sc, h[0], l[0]);
    hsplit(v.y * sc, h[1], l[1]);
    hsplit(v.z * sc, h[2], l[2]);
    hsplit(v.w * sc, h[3], l[3]);
    const int mt = m >> 7, ml = m & 127, cs = k0 >> 4, ko = k0 & 15;
    const int dst = ((mt * 16 + cs) * 128 + ml) * 16 + ko;
    *(uint2*)&g_wh[dst] = *(uint2*)h;
    *(uint2*)&g_wl[dst] = *(uint2*)l;
}

// ---------------- pre-pass: transpose+convert x to hi/lo chunk-major -------
__global__ __launch_bounds__(256) void k_cvt_x(const float* __restrict__ x)
{
    __shared__ float tile[16][260];
    const int cc = blockIdx.x >> 2;          // k-chunk 0..15
    const int ng = blockIdx.x & 3;           // n-group (256 cols)
    const int b  = blockIdx.y;
    const int tid = threadIdx.x;
#pragma unroll
    for (int i = 0; i < 4; ++i) {
        int idx = tid + i * 256;             // 0..1023
        int r = idx >> 6, c4 = (idx & 63) * 4;
        float4 v = *(const float4*)&x[b * (NCIN * NPIX) + (cc * 16 + r) * NPIX
                                      + ng * 256 + c4];
        tile[r][c4 + 0] = v.x; tile[r][c4 + 1] = v.y;
        tile[r][c4 + 2] = v.z; tile[r][c4 + 3] = v.w;
    }
    __syncthreads();
    __half h[16], l[16];
#pragma unroll
    for (int k = 0; k < 16; ++k) hsplit(tile[k][tid], h[k], l[k]);
    const int dst = ((b * 16 + cc) * 1024 + ng * 256 + tid) * 16;
    *(uint4*)&g_xh[dst]     = *(uint4*)&h[0];
    *(uint4*)&g_xh[dst + 8] = *(uint4*)&h[8];
    *(uint4*)&g_xl[dst]     = *(uint4*)&l[0];
    *(uint4*)&g_xl[dst + 8] = *(uint4*)&l[8];
}

// ---------------- kernel 1: tensor-core fused projection (R10-verified) ----
#define SSTR 132
__global__ __launch_bounds__(256, 2) void k_proj(
    const float* __restrict__ b_qkv, const float* __restrict__ b_out,
    float* __restrict__ out)
{
    __shared__ __align__(16) char smraw[24576];
    __half* sAh = (__half*)smraw;            // [128 m][24]
    __half* sAl = (__half*)smraw + 3072;
    __half* sBh = (__half*)smraw + 6144;     // [128 n][24]
    __half* sBl = (__half*)smraw + 9216;
    float*  S   = (float*)smraw;             // epilogue alias [32][SSTR]

    const int b  = blockIdx.z;
    const int mt = blockIdx.y;               // 0=q 1=k 2=v 3=conv
    const int n0 = blockIdx.x * 128;
    const int tid = threadIdx.x;
    const int w    = tid >> 5;
    const int lane = tid & 31;
    const int gid = lane >> 2, tig = lane & 3;
    const int wm = w & 3;                    // m-quarter (32 rows)
    const int wn = w >> 2;                   // n-half (64 cols)

    const int sm_row = tid >> 1;             // m or n row 0..127
    const int sm_hp  = tid & 1;              // which 8-half group of chunk

    const __half* wsrch = g_wh + (mt * 16) * 128 * 16;
    const __half* wsrcl = g_wl + (mt * 16) * 128 * 16;
    const __half* xsrch = g_xh + ((u64)b * 16) * 1024 * 16;
    const __half* xsrcl = g_xl + ((u64)b * 16) * 1024 * 16;
    const int aoff = sm_row * 16 + sm_hp * 8;
    const int boff = (n0 + sm_row) * 16 + sm_hp * 8;

    uint4 pah, pal, pbh, pbl;
    pah = *(const uint4*)&wsrch[aoff];
    pal = *(const uint4*)&wsrcl[aoff];
    pbh = *(const uint4*)&xsrch[boff];
    pbl = *(const uint4*)&xsrcl[boff];

    float4 c[2][8];
#pragma unroll
    for (int t = 0; t < 2; ++t)
#pragma unroll
        for (int nb = 0; nb < 8; ++nb) c[t][nb] = make_float4(0.f, 0.f, 0.f, 0.f);

    for (int cs = 0; cs < 16; ++cs) {
        __syncthreads();
        *(uint4*)&sAh[sm_row * 24 + sm_hp * 8] = pah;
        *(uint4*)&sAl[sm_row * 24 + sm_hp * 8] = pal;
        *(uint4*)&sBh[sm_row * 24 + sm_hp * 8] = pbh;
        *(uint4*)&sBl[sm_row * 24 + sm_hp * 8] = pbl;
        __syncthreads();
        if (cs < 15) {
            const int anext = (cs + 1) * 128 * 16 + aoff;
            const int bnext = (cs + 1) * 1024 * 16 + boff;
            pah = *(const uint4*)&wsrch[anext];
            pal = *(const uint4*)&wsrcl[anext];
            pbh = *(const uint4*)&xsrch[bnext];
            pbl = *(const uint4*)&xsrcl[bnext];
        }

        const u32* Ahw = (const u32*)sAh;
        const u32* Alw = (const u32*)sAl;
        const u32* Bhw = (const u32*)sBh;
        const u32* Blw = (const u32*)sBl;

        u32 ah[2][4], al[2][4];
#pragma unroll
        for (int t = 0; t < 2; ++t) {
            int r0 = wm * 32 + t * 16 + gid;
            ah[t][0] = Ahw[r0 * 12 + tig];
            ah[t][1] = Ahw[(r0 + 8) * 12 + tig];
            ah[t][2] = Ahw[r0 * 12 + tig + 4];
            ah[t][3] = Ahw[(r0 + 8) * 12 + tig + 4];
            al[t][0] = Alw[r0 * 12 + tig];
            al[t][1] = Alw[(r0 + 8) * 12 + tig];
            al[t][2] = Alw[r0 * 12 + tig + 4];
            al[t][3] = Alw[(r0 + 8) * 12 + tig + 4];
        }
        u32 bf[8][2];
#pragma unroll
        for (int nb = 0; nb < 8; ++nb) {
            int n = wn * 64 + nb * 8 + gid;
            bf[nb][0] = Bhw[n * 12 + tig];
            bf[nb][1] = Bhw[n * 12 + tig + 4];
        }
#pragma unroll
        for (int nb = 0; nb < 8; ++nb) {
            mma16816(c[0][nb], ah[0], bf[nb][0], bf[nb][1]);
            mma16816(c[1][nb], ah[1], bf[nb][0], bf[nb][1]);
            mma16816(c[0][nb], al[0], bf[nb][0], bf[nb][1]);
            mma16816(c[1][nb], al[1], bf[nb][0], bf[nb][1]);
        }
#pragma unroll
        for (int nb = 0; nb < 8; ++nb) {
            int n = wn * 64 + nb * 8 + gid;
            bf[nb][0] = Blw[n * 12 + tig];
            bf[nb][1] = Blw[n * 12 + tig + 4];
        }
#pragma unroll
        for (int nb = 0; nb < 8; ++nb) {
            mma16816(c[0][nb], ah[0], bf[nb][0], bf[nb][1]);
            mma16816(c[1][nb], ah[1], bf[nb][0], bf[nb][1]);
        }
    }

    const float wscale = (mt == 0) ? 0.25f : 1.0f;
    float bias[2][2];
#pragma unroll
    for (int t = 0; t < 2; ++t) {
        int m = wm * 32 + t * 16 + gid;
        if (mt < 3) {
            bias[t][0] = b_qkv[mt * 128 + m] * wscale;
            bias[t][1] = b_qkv[mt * 128 + m + 8] * wscale;
        } else {
            bias[t][0] = b_out[m];
            bias[t][1] = b_out[m + 8];
        }
    }
#pragma unroll
    for (int t = 0; t < 2; ++t)
#pragma unroll
        for (int nb = 0; nb < 8; ++nb) {
            c[t][nb].x += bias[t][0]; c[t][nb].y += bias[t][0];
            c[t][nb].z += bias[t][1]; c[t][nb].w += bias[t][1];
        }

    for (int mc = 0; mc < 4; ++mc) {
        __syncthreads();
        if (wm == mc) {
#pragma unroll
            for (int t = 0; t < 2; ++t)
#pragma unroll
                for (int nb = 0; nb < 8; ++nb) {
                    int col = wn * 64 + nb * 8 + tig * 2;
                    int r0 = t * 16 + gid;
                    *(float2*)&S[r0 * SSTR + col]       = make_float2(c[t][nb].x, c[t][nb].y);
                    *(float2*)&S[(r0 + 8) * SSTR + col] = make_float2(c[t][nb].z, c[t][nb].w);
                }
        }
        __syncthreads();

        if (mt == 3) {
#pragma unroll
            for (int t = 0; t < 4; ++t) {
                int idx = tid + t * 256;
                int nq = idx & 31, row = idx >> 5;
                float4 v = *(const float4*)&S[row * SSTR + nq * 4];
                *(float4*)&out[b * 262144 + (mc * 32 + row) * NPIX + n0 + nq * 4] = v;
            }
        } else if (mt == 2) {
#pragma unroll
            for (int t = 0; t < 2; ++t) {
                int idx = tid + t * 256;
                int noct = idx & 15, row = idx >> 4;
                const float* sp = &S[row * SSTR + noct * 8];
                uint4 u;
                u.x = h2u(__floats2half2_rn(sp[0], sp[1]));
                u.y = h2u(__floats2half2_rn(sp[2], sp[3]));
                u.z = h2u(__floats2half2_rn(sp[4], sp[5]));
                u.w = h2u(__floats2half2_rn(sp[6], sp[7]));
                int h = mc * 2 + (row >> 4);
                int d = row & 15;
                *(uint4*)&g_vt[(((b * 8 + h) * 16 + d) << 10) + n0 + noct * 8] = u;
            }
        } else {
            __half* g = (mt == 0) ? g_qh : g_kh;
#pragma unroll
            for (int t = 0; t < 2; ++t) {
                int idx = tid + t * 256;
                int n = idx & 127;
                int rest = idx >> 7;
                int hsel = rest >> 1, dh = rest & 1;
                int rb = hsel * 16 + dh * 8;
                uint4 u;
                u.x = h2u(__floats2half2_rn(S[(rb + 0) * SSTR + n], S[(rb + 1) * SSTR + n]));
                u.y = h2u(__floats2half2_rn(S[(rb + 2) * SSTR + n], S[(rb + 3) * SSTR + n]));
                u.z = h2u(__floats2half2_rn(S[(rb + 4) * SSTR + n], S[(rb + 5) * SSTR + n]));
                u.w = h2u(__floats2half2_rn(S[(rb + 6) * SSTR + n], S[(rb + 7) * SSTR + n]));
                int bh = b * 8 + mc * 2 + hsel;
                *(uint4*)&g[((u64)bh << 14) + (u64)(n0 + n) * 16 + dh * 8] = u;
            }
        }
    }
}

// ---------------- kernel 2: tensor-core attention ---------------------------
// K split into two unpadded [1024][8] arrays (k 0-7 / 8-15): stride-4-word
// frag loads hit all 32 banks; smem 65792 B -> 3 CTAs/SM.
#define VROW 1032     // halves per Vt row (516 words)
__global__ __launch_bounds__(256, 3) void k_attn()
{
    extern __shared__ __half sm[];
    __half* Ka = sm;                    // [1024][8]  k dims 0..7
    __half* Kb = sm + 8192;             // [1024][8]  k dims 8..15
    __half* Vt = sm + 16384;            // [16][VROW]
    const int qb  = blockIdx.x;
    const int bh  = blockIdx.y;
    const int tid = threadIdx.x;
    const int w   = tid >> 5;
    const int lane = tid & 31;
    const int gid = lane >> 2, tig = lane & 3;
    const u64 ONE = make2(1.0f);

    const uint4* ksrc = (const uint4*)(g_kh + ((u64)bh << 14));
    const uint4* vsrc = (const uint4*)(g_vt + ((u64)bh << 14));
#pragma unroll
    for (int j = 0; j < 8; ++j) {
        int idx = tid + j * 256;
        int seq = idx >> 1, hp = idx & 1;
        __half* kd = hp ? Kb : Ka;
        *(uint4*)&kd[seq * 8] = ksrc[idx];
    }
#pragma unroll
    for (int j = 0; j < 8; ++j) {
        int idx = tid + j * 256;
        int row = idx >> 7, off = (idx & 127) * 8;
        *(uint4*)&Vt[row * VROW + off] = vsrc[idx];
    }

    const __half* qp = g_qh + ((u64)bh << 14) + (qb * 128 + w * 16) * 16;
    u32 aq[4];
    aq[0] = *(const u32*)(qp + gid * 16 + tig * 2);
    aq[1] = *(const u32*)(qp + (gid + 8) * 16 + tig * 2);
    aq[2] = *(const u32*)(qp + gid * 16 + tig * 2 + 8);
    aq[3] = *(const u32*)(qp + (gid + 8) * 16 + tig * 2 + 8);
    __syncthreads();

    float4 o0 = make_float4(0.f, 0.f, 0.f, 0.f);
    float4 o1 = make_float4(0.f, 0.f, 0.f, 0.f);
    u64 l2a = 0ull, l2b = 0ull;

    const u32* kaw = (const u32*)Ka;
    const u32* kbw = (const u32*)Kb;
    const u32* vw  = (const u32*)Vt;

#pragma unroll 2
    for (int n0 = 0; n0 < NPIX; n0 += 16) {
        u32 kb00 = kaw[(n0 + gid) * 4 + tig];
        u32 kb01 = kbw[(n0 + gid) * 4 + tig];
        u32 kb10 = kaw[(n0 + 8 + gid) * 4 + tig];
        u32 kb11 = kbw[(n0 + 8 + gid) * 4 + tig];
        float4 s0 = make_float4(0.f, 0.f, 0.f, 0.f);
        float4 s1 = make_float4(0.f, 0.f, 0.f, 0.f);
        mma16816(s0, aq, kb00, kb01);
        mma16816(s1, aq, kb10, kb11);

        u64 e0 = exp_dual(pack2(s0.x, s0.y));
        u64 e1 = exp_dual(pack2(s0.z, s0.w));
        u64 e2 = exp_dual(pack2(s1.x, s1.y));
        u64 e3 = exp_dual(pack2(s1.z, s1.w));
        l2a = fma2(e0, ONE, l2a); l2a = fma2(e2, ONE, l2a);
        l2b = fma2(e1, ONE, l2b); l2b = fma2(e3, ONE, l2b);

        // P fragments: hi only (fp16-rn error -> ~1e-4 output, verified R12)
        float2 f0 = unpack2(e0), f1 = unpack2(e1), f2 = unpack2(e2), f3 = unpack2(e3);
        u32 ph[4] = {h2u(__floats2half2_rn(f0.x, f0.y)),
                     h2u(__floats2half2_rn(f1.x, f1.y)),
                     h2u(__floats2half2_rn(f2.x, f2.y)),
                     h2u(__floats2half2_rn(f3.x, f3.y))};

        u32 vb00 = vw[gid * 516 + (n0 >> 1) + tig];
        u32 vb01 = vw[gid * 516 + (n0 >> 1) + tig + 4];
        u32 vb10 = vw[(gid + 8) * 516 + (n0 >> 1) + tig];
        u32 vb11 = vw[(gid + 8) * 516 + (n0 >> 1) + tig + 4];

        mma16816(o0, ph, vb00, vb01);
        mma16816(o1, ph, vb10, vb11);
    }

    float2 lA = unpack2(l2a), lB = unpack2(l2b);
    float lr0 = lA.x + lA.y;
    float lr8 = lB.x + lB.y;
    lr0 += __shfl_xor_sync(0xFFFFFFFFu, lr0, 1);
    lr0 += __shfl_xor_sync(0xFFFFFFFFu, lr0, 2);
    lr8 += __shfl_xor_sync(0xFFFFFFFFu, lr8, 1);
    lr8 += __shfl_xor_sync(0xFFFFFFFFu, lr8, 2);
    float i0 = 1.0f / lr0, i8 = 1.0f / lr8;

    const int b = bh >> 3, h = bh & 7;
    float* ob = g_attn + b * (128 * NPIX) + h * (16 * NPIX);
    const int seq0 = qb * 128 + w * 16 + gid;
    const int d0 = tig * 2;
    ob[(d0 + 0) * NPIX + seq0]     = o0.x * i0;
    ob[(d0 + 1) * NPIX + seq0]     = o0.y * i0;
    ob[(d0 + 0) * NPIX + seq0 + 8] = o0.z * i8;
    ob[(d0 + 1) * NPIX + seq0 + 8] = o0.w * i8;
    ob[(d0 + 8) * NPIX + seq0]     = o1.x * i0;
    ob[(d0 + 9) * NPIX + seq0]     = o1.y * i0;
    ob[(d0 + 8) * NPIX + seq0 + 8] = o1.z * i8;
    ob[(d0 + 9) * NPIX + seq0 + 8] = o1.w * i8;
}

// ---------------- kernel 3: attn output projection (unchanged, FFMA2) ------
__global__ __launch_bounds__(256, 2) void k_attnproj(
    const float* __restrict__ w_attn, const float* __restrict__ b_attn,
    float* __restrict__ out)
{
    __shared__ float As[16][128];
    __shared__ float Bs[16][128];
    const int b  = blockIdx.z;
    const int n0 = blockIdx.x * 128;
    const int tid = threadIdx.x;
    const int tx = tid & 15;
    const int ty = tid >> 4;
    const float* Bsrc = g_attn + b * (128 * NPIX);

    const int a_ml0 = tid & 127, a_kq0 = (tid >> 7);
    const int b_kl0 = tid >> 5, b_nl0 = (tid & 31) * 4;

    float4 ar[2], br[2];
    ar[0] = *(const float4*)&w_attn[a_ml0 * 128 + a_kq0 * 4];
    ar[1] = *(const float4*)&w_attn[a_ml0 * 128 + (a_kq0 + 2) * 4];
    br[0] = *(const float4*)&Bsrc[b_kl0 * NPIX + n0 + b_nl0];
    br[1] = *(const float4*)&Bsrc[(b_kl0 + 8) * NPIX + n0 + b_nl0];

    u64 acc[8][4];
#pragma unroll
    for (int i = 0; i < 8; ++i)
#pragma unroll
        for (int j = 0; j < 4; ++j) acc[i][j] = 0ull;

    for (int c = 0; c < 8; ++c) {
        __syncthreads();
#pragma unroll
        for (int r = 0; r < 2; ++r) {
            int kq = a_kq0 + r * 2;
            As[kq * 4 + 0][a_ml0] = ((float*)&ar[r])[0];
            As[kq * 4 + 1][a_ml0] = ((float*)&ar[r])[1];
            As[kq * 4 + 2][a_ml0] = ((float*)&ar[r])[2];
            As[kq * 4 + 3][a_ml0] = ((float*)&ar[r])[3];
        }
        *(float4*)&Bs[b_kl0][b_nl0]     = br[0];
        *(float4*)&Bs[b_kl0 + 8][b_nl0] = br[1];
        __syncthreads();
        if (c < 7) {
            int k0 = (c + 1) * 16;
            ar[0] = *(const float4*)&w_attn[a_ml0 * 128 + k0 + a_kq0 * 4];
            ar[1] = *(const float4*)&w_attn[a_ml0 * 128 + k0 + (a_kq0 + 2) * 4];
            br[0] = *(const float4*)&Bsrc[(k0 + b_kl0) * NPIX + n0 + b_nl0];
            br[1] = *(const float4*)&Bsrc[(k0 + b_kl0 + 8) * NPIX + n0 + b_nl0];
        }
#pragma unroll
        for (int kk = 0; kk < 16; ++kk) {
            float4 a0 = *(const float4*)&As[kk][ty * 8];
            float4 a1 = *(const float4*)&As[kk][ty * 8 + 4];
            ulonglong2 b01 = *(const ulonglong2*)&Bs[kk][tx * 8];
            ulonglong2 b23 = *(const ulonglong2*)&Bs[kk][tx * 8 + 4];
            u64 bp[4] = {b01.x, b01.y, b23.x, b23.y};
            float am[8] = {a0.x, a0.y, a0.z, a0.w, a1.x, a1.y, a1.z, a1.w};
#pragma unroll
            for (int i = 0; i < 8; ++i) {
                u64 ad = pack2(am[i], am[i]);
#pragma unroll
                for (int j = 0; j < 4; ++j)
                    acc[i][j] = fma2(ad, bp[j], acc[i][j]);
            }
        }
    }

#pragma unroll
    for (int i = 0; i < 8; ++i) {
        int m = ty * 8 + i;
        float bias = b_attn[m];
        float v[8];
#pragma unroll
        for (int j = 0; j < 4; ++j) {
            float2 t = unpack2(acc[i][j]);
            v[j * 2 + 0] = t.x + bias;
            v[j * 2 + 1] = t.y + bias;
        }
        float* dst = out + b * 262144 + (128 + m) * NPIX + n0 + tx * 8;
        *(float4*)dst       = make_float4(v[0], v[1], v[2], v[3]);
        *(float4*)(dst + 4) = make_float4(v[4], v[5], v[6], v[7]);
    }
}

// ---------------- launch ----------------------------------------------------
extern "C" void kernel_launch(void* const* d_in, const int* in_sizes, int n_in,
                              void* d_out, int out_size)
{
    const float* x      = (const float*)d_in[0];
    const float* w_qkv  = (const float*)d_in[1];
    const float* b_qkv  = (const float*)d_in[2];
    const float* w_attn = (const float*)d_in[3];
    const float* b_attn = (const float*)d_in[4];
    const float* w_out  = (const float*)d_in[5];
    const float* b_out  = (const float*)d_in[6];
    float* out = (float*)d_out;

    k_cvt_w<<<512, 64>>>(w_qkv, w_out);
    dim3 gc(64, 32);
    k_cvt_x<<<gc, 256>>>(x);

    dim3 g1(8, 4, 32);                 // n-tiles(128), m-tiles(q/k/v/conv), batch
    k_proj<<<g1, 256>>>(b_qkv, b_out, out);

    const int smem_attn = (1024 * 16 + 16 * VROW) * (int)sizeof(__half); // 65792
    cudaFuncSetAttribute(k_attn, cudaFuncAttributeMaxDynamicSharedMemorySize,
                         smem_attn);
    dim3 g2(8, 256);                   // q-blocks x (b,h)
    k_attn<<<g2, 256, smem_attn>>>();

    dim3 g3(8, 1, 32);
    k_attnproj<<<g3, 256>>>(w_attn, b_attn, out);
}

// round 14
// speedup vs baseline: 1.9736x; 1.1597x over previous
#include <cuda_runtime.h>
#include <cuda_fp16.h>

// ---------------- problem constants ----------------
// B=32, CIN=256, H=W=32 (N=1024), DK=DV=128, HEADS=8, DKH=DVH=16, OUT=256
#define NB    32
#define NPIX  1024
#define NCIN  256

typedef unsigned long long u64;
typedef unsigned int u32;

// ---------------- scratch (static device mem; no allocations allowed) ------
__device__ __half g_qh[32 * 8 * 1024 * 16];   // [bh][n][16]  (pre-scaled 0.25)
__device__ __half g_kh[32 * 8 * 1024 * 16];   // [bh][n][16]
__device__ __half g_vt[32 * 8 * 16 * 1024];   // [bh][d][n]   (transposed)
__device__ float  g_attn[32 * 128 * 1024];    // [b][dv][n]
// pre-converted fp16 operands (chunk-major for coalesced staging)
__device__ __half g_wh[4 * 16 * 128 * 16];    // [mt][cs][128m][16k]  weights hi
__device__ __half g_wl[4 * 16 * 128 * 16];    // weights lo
__device__ __half g_xh[32 * 16 * 1024 * 16];  // [b][cs][1024n][16k]  x hi only

// ---------------- packed f32x2 helpers -------------------------------------
__device__ __forceinline__ u64 fma2(u64 a, u64 b, u64 c) {
    u64 d;
    asm("fma.rn.f32x2 %0, %1, %2, %3;" : "=l"(d) : "l"(a), "l"(b), "l"(c));
    return d;
}
__device__ __forceinline__ u64 pack2(float lo, float hi) {
    u64 d;
    asm("mov.b64 %0, {%1, %2};" : "=l"(d) : "f"(lo), "f"(hi));
    return d;
}
__device__ __forceinline__ float2 unpack2(u64 v) {
    float2 r;
    asm("mov.b64 {%0, %1}, %2;" : "=f"(r.x), "=f"(r.y) : "l"(v));
    return r;
}
__device__ __forceinline__ void split64(u64 v, u32& lo, u32& hi) {
    asm("mov.b64 {%0, %1}, %2;" : "=r"(lo), "=r"(hi) : "l"(v));
}
__device__ __forceinline__ u64 join64(u32 lo, u32 hi) {
    u64 d;
    asm("mov.b64 %0, {%1, %2};" : "=l"(d) : "r"(lo), "r"(hi));
    return d;
}
__device__ __forceinline__ u64 make2(float v) { return pack2(v, v); }
__device__ __forceinline__ u32 h2u(__half2 h) {
    union { __half2 h; u32 u; } c; c.h = h; return c.u;
}

// ---------------- dual packed exp, 6 fma2 + ALU bits-add --------------------
// Range: r = RN(y+MAGIC), -i = MAGIC-r (exact), f = y-i in [-0.5,0.5].
// Poly: deg-3 Chebyshev-economized for 2^f (c2 absorbs f^4 term; c0 trimmed).
// Max rel err ~1.1e-4, common-mode in softmax. Scale 2^i via exponent-bit add.
__device__ __forceinline__ u64 exp_dual(u64 s2) {
    const u64 NEG1  = make2(-1.0f);
    const u64 L2E   = make2(1.4426950408889634f);
    const u64 MAGIC = make2(12582912.0f);            // 2^23 + 2^22
    const u64 C3 = make2(5.5504109e-2f);
    const u64 C2 = make2(2.4263210e-1f);             // 0.240227 + economized f^4
    const u64 C1 = make2(6.9314718e-1f);
    const u64 C0 = make2(9.9992490e-1f);
    u64 r  = fma2(s2, L2E, MAGIC);      // y + magic (RN -> i in mantissa)
    u64 mr = fma2(r, NEG1, MAGIC);      // -i (exact)
    u64 f  = fma2(s2, L2E, mr);         // f = y - i in [-0.5, 0.5]
    u64 p  = fma2(C3, f, C2);
    p = fma2(p, f, C1);
    p = fma2(p, f, C0);                 // p ~= 2^f in [0.707, 1.415]
    u32 rl, rh, pl, ph;
    split64(r, rl, rh);
    split64(p, pl, ph);
    return join64(pl + (rl << 23), ph + (rh << 23));   // p * 2^i (bit-exact)
}

// ---------------- mma.sync m16n8k16 fp16 -> fp32 ---------------------------
__device__ __forceinline__ void mma16816(float4& c, const u32* a, u32 b0, u32 b1) {
    asm volatile(
        "mma.sync.aligned.m16n8k16.row.col.f32.f16.f16.f32 "
        "{%0,%1,%2,%3}, {%4,%5,%6,%7}, {%8,%9}, {%0,%1,%2,%3};"
        : "+f"(c.x), "+f"(c.y), "+f"(c.z), "+f"(c.w)
        : "r"(a[0]), "r"(a[1]), "r"(a[2]), "r"(a[3]), "r"(b0), "r"(b1));
}

__device__ __forceinline__ void hsplit(float v, __half& hi, __half& lo) {
    hi = __float2half_rn(v);
    lo = __float2half_rn(v - __half2float(hi));
}

// ---------------- pre-pass: convert weights to hi/lo fp16 chunk-major ------
__global__ void k_cvt_w(const float* __restrict__ w_qkv,
                        const float* __restrict__ w_out)
{
    const int m = blockIdx.x;
    const int k0 = threadIdx.x * 4;
    const float* src = (m < 384) ? &w_qkv[m * NCIN + k0]
                                 : &w_out[(m - 384) * NCIN + k0];
    const float sc = (m < 128) ? 0.25f : 1.0f;
    float4 v = *(const float4*)src;
    __half h[4], l[4];
    hsplit(v.x * sc, h[0], l[0]);
    hsplit(v.y * sc, h[1], l[1]);
    hsplit(v.z * sc, h[2], l[2]);
    hsplit(v.w * sc, h[3], l[3]);
    const int mt = m >> 7, ml = m & 127, cs = k0 >> 4, ko = k0 & 15;
    const int dst = ((mt * 16 + cs) * 128 + ml) * 16 + ko;
    *(uint2*)&g_wh[dst] = *(uint2*)h;
    *(uint2*)&g_wl[dst] = *(uint2*)l;
}

// ---------------- pre-pass: transpose+convert x to fp16 hi chunk-major -----
__global__ __launch_bounds__(256) void k_cvt_x(const float* __restrict__ x)
{
    __shared__ float tile[16][260];
    const int cc = blockIdx.x >> 2;          // k-chunk 0..15
    const int ng = blockIdx.x & 3;           // n-group (256 cols)
    const int b  = blockIdx.y;
    const int tid = threadIdx.x;
#pragma unroll
    for (int i = 0; i < 4; ++i) {
        int idx = tid + i * 256;             // 0..1023
        int r = idx >> 6, c4 = (idx & 63) * 4;
        float4 v = *(const float4*)&x[b * (NCIN * NPIX) + (cc * 16 + r) * NPIX
                                      + ng * 256 + c4];
        tile[r][c4 + 0] = v.x; tile[r][c4 + 1] = v.y;
        tile[r][c4 + 2] = v.z; tile[r][c4 + 3] = v.w;
    }
    __syncthreads();
    __half h[16];
#pragma unroll
    for (int k = 0; k < 16; ++k) h[k] = __float2half_rn(tile[k][tid]);
    const int dst = ((b * 16 + cc) * 1024 + ng * 256 + tid) * 16;
    *(uint4*)&g_xh[dst]     = *(uint4*)&h[0];
    *(uint4*)&g_xh[dst + 8] = *(uint4*)&h[8];
}

// ---------------- kernel 1: tensor-core fused projection -------------------
// 2-term split: Ah*Bh + Al*Bh (x-lo dropped; ~1.4e-4 output rel err).
#define SSTR 132
__global__ __launch_bounds__(256, 2) void k_proj(
    const float* __restrict__ b_qkv, const float* __restrict__ b_out,
    float* __restrict__ out)
{
    __shared__ __align__(16) char smraw[24576];
    __half* sAh = (__half*)smraw;            // [128 m][24]
    __half* sAl = (__half*)smraw + 3072;
    __half* sBh = (__half*)smraw + 6144;     // [128 n][24]
    float*  S   = (float*)smraw;             // epilogue alias [32][SSTR]

    const int b  = blockIdx.z;
    const int mt = blockIdx.y;               // 0=q 1=k 2=v 3=conv
    const int n0 = blockIdx.x * 128;
    const int tid = threadIdx.x;
    const int w    = tid >> 5;
    const int lane = tid & 31;
    const int gid = lane >> 2, tig = lane & 3;
    const int wm = w & 3;                    // m-quarter (32 rows)
    const int wn = w >> 2;                   // n-half (64 cols)

    const int sm_row = tid >> 1;             // m or n row 0..127
    const int sm_hp  = tid & 1;              // which 8-half group of chunk

    const __half* wsrch = g_wh + (mt * 16) * 128 * 16;
    const __half* wsrcl = g_wl + (mt * 16) * 128 * 16;
    const __half* xsrch = g_xh + ((u64)b * 16) * 1024 * 16;
    const int aoff = sm_row * 16 + sm_hp * 8;
    const int boff = (n0 + sm_row) * 16 + sm_hp * 8;

    uint4 pah, pal, pbh;
    pah = *(const uint4*)&wsrch[aoff];
    pal = *(const uint4*)&wsrcl[aoff];
    pbh = *(const uint4*)&xsrch[boff];

    float4 c[2][8];
#pragma unroll
    for (int t = 0; t < 2; ++t)
#pragma unroll
        for (int nb = 0; nb < 8; ++nb) c[t][nb] = make_float4(0.f, 0.f, 0.f, 0.f);

    for (int cs = 0; cs < 16; ++cs) {
        __syncthreads();
        *(uint4*)&sAh[sm_row * 24 + sm_hp * 8] = pah;
        *(uint4*)&sAl[sm_row * 24 + sm_hp * 8] = pal;
        *(uint4*)&sBh[sm_row * 24 + sm_hp * 8] = pbh;
        __syncthreads();
        if (cs < 15) {
            const int anext = (cs + 1) * 128 * 16 + aoff;
            const int bnext = (cs + 1) * 1024 * 16 + boff;
            pah = *(const uint4*)&wsrch[anext];
            pal = *(const uint4*)&wsrcl[anext];
            pbh = *(const uint4*)&xsrch[bnext];
        }

        const u32* Ahw = (const u32*)sAh;
        const u32* Alw = (const u32*)sAl;
        const u32* Bhw = (const u32*)sBh;

        u32 ah[2][4], al[2][4];
#pragma unroll
        for (int t = 0; t < 2; ++t) {
            int r0 = wm * 32 + t * 16 + gid;
            ah[t][0] = Ahw[r0 * 12 + tig];
            ah[t][1] = Ahw[(r0 + 8) * 12 + tig];
            ah[t][2] = Ahw[r0 * 12 + tig + 4];
            ah[t][3] = Ahw[(r0 + 8) * 12 + tig + 4];
            al[t][0] = Alw[r0 * 12 + tig];
            al[t][1] = Alw[(r0 + 8) * 12 + tig];
            al[t][2] = Alw[r0 * 12 + tig + 4];
            al[t][3] = Alw[(r0 + 8) * 12 + tig + 4];
        }
        u32 bf[8][2];
#pragma unroll
        for (int nb = 0; nb < 8; ++nb) {
            int n = wn * 64 + nb * 8 + gid;
            bf[nb][0] = Bhw[n * 12 + tig];
            bf[nb][1] = Bhw[n * 12 + tig + 4];
        }
#pragma unroll
        for (int nb = 0; nb < 8; ++nb) {
            mma16816(c[0][nb], ah[0], bf[nb][0], bf[nb][1]);
            mma16816(c[1][nb], ah[1], bf[nb][0], bf[nb][1]);
            mma16816(c[0][nb], al[0], bf[nb][0], bf[nb][1]);
            mma16816(c[1][nb], al[1], bf[nb][0], bf[nb][1]);
        }
    }

    const float wscale = (mt == 0) ? 0.25f : 1.0f;
    float bias[2][2];
#pragma unroll
    for (int t = 0; t < 2; ++t) {
        int m = wm * 32 + t * 16 + gid;
        if (mt < 3) {
            bias[t][0] = b_qkv[mt * 128 + m] * wscale;
            bias[t][1] = b_qkv[mt * 128 + m + 8] * wscale;
        } else {
            bias[t][0] = b_out[m];
            bias[t][1] = b_out[m + 8];
        }
    }
#pragma unroll
    for (int t = 0; t < 2; ++t)
#pragma unroll
        for (int nb = 0; nb < 8; ++nb) {
            c[t][nb].x += bias[t][0]; c[t][nb].y += bias[t][0];
            c[t][nb].z += bias[t][1]; c[t][nb].w += bias[t][1];
        }

    for (int mc = 0; mc < 4; ++mc) {
        __syncthreads();
        if (wm == mc) {
#pragma unroll
            for (int t = 0; t < 2; ++t)
#pragma unroll
                for (int nb = 0; nb < 8; ++nb) {
                    int col = wn * 64 + nb * 8 + tig * 2;
                    int r0 = t * 16 + gid;
                    *(float2*)&S[r0 * SSTR + col]       = make_float2(c[t][nb].x, c[t][nb].y);
                    *(float2*)&S[(r0 + 8) * SSTR + col] = make_float2(c[t][nb].z, c[t][nb].w);
                }
        }
        __syncthreads();

        if (mt == 3) {
#pragma unroll
            for (int t = 0; t < 4; ++t) {
                int idx = tid + t * 256;
                int nq = idx & 31, row = idx >> 5;
                float4 v = *(const float4*)&S[row * SSTR + nq * 4];
                *(float4*)&out[b * 262144 + (mc * 32 + row) * NPIX + n0 + nq * 4] = v;
            }
        } else if (mt == 2) {
#pragma unroll
            for (int t = 0; t < 2; ++t) {
                int idx = tid + t * 256;
                int noct = idx & 15, row = idx >> 4;
                const float* sp = &S[row * SSTR + noct * 8];
                uint4 u;
                u.x = h2u(__floats2half2_rn(sp[0], sp[1]));
                u.y = h2u(__floats2half2_rn(sp[2], sp[3]));
                u.z = h2u(__floats2half2_rn(sp[4], sp[5]));
                u.w = h2u(__floats2half2_rn(sp[6], sp[7]));
                int h = mc * 2 + (row >> 4);
                int d = row & 15;
                *(uint4*)&g_vt[(((b * 8 + h) * 16 + d) << 10) + n0 + noct * 8] = u;
            }
        } else {
            __half* g = (mt == 0) ? g_qh : g_kh;
#pragma unroll
            for (int t = 0; t < 2; ++t) {
                int idx = tid + t * 256;
                int n = idx & 127;
                int rest = idx >> 7;
                int hsel = rest >> 1, dh = rest & 1;
                int rb = hsel * 16 + dh * 8;
                uint4 u;
                u.x = h2u(__floats2half2_rn(S[(rb + 0) * SSTR + n], S[(rb + 1) * SSTR + n]));
                u.y = h2u(__floats2half2_rn(S[(rb + 2) * SSTR + n], S[(rb + 3) * SSTR + n]));
                u.z = h2u(__floats2half2_rn(S[(rb + 4) * SSTR + n], S[(rb + 5) * SSTR + n]));
                u.w = h2u(__floats2half2_rn(S[(rb + 6) * SSTR + n], S[(rb + 7) * SSTR + n]));
                int bh = b * 8 + mc * 2 + hsel;
                *(uint4*)&g[((u64)bh << 14) + (u64)(n0 + n) * 16 + dh * 8] = u;
            }
        }
    }
}

// ---------------- kernel 2: tensor-core attention (R13 layout, deg-3 exp) --
#define VROW 1032     // halves per Vt row (516 words)
__global__ __launch_bounds__(256, 3) void k_attn()
{
    extern __shared__ __half sm[];
    __half* Ka = sm;                    // [1024][8]  k dims 0..7
    __half* Kb = sm + 8192;             // [1024][8]  k dims 8..15
    __half* Vt = sm + 16384;            // [16][VROW]
    const int qb  = blockIdx.x;
    const int bh  = blockIdx.y;
    const int tid = threadIdx.x;
    const int w   = tid >> 5;
    const int lane = tid & 31;
    const int gid = lane >> 2, tig = lane & 3;
    const u64 ONE = make2(1.0f);

    const uint4* ksrc = (const uint4*)(g_kh + ((u64)bh << 14));
    const uint4* vsrc = (const uint4*)(g_vt + ((u64)bh << 14));
#pragma unroll
    for (int j = 0; j < 8; ++j) {
        int idx = tid + j * 256;
        int seq = idx >> 1, hp = idx & 1;
        __half* kd = hp ? Kb : Ka;
        *(uint4*)&kd[seq * 8] = ksrc[idx];
    }
#pragma unroll
    for (int j = 0; j < 8; ++j) {
        int idx = tid + j * 256;
        int row = idx >> 7, off = (idx & 127) * 8;
        *(uint4*)&Vt[row * VROW + off] = vsrc[idx];
    }

    const __half* qp = g_qh + ((u64)bh << 14) + (qb * 128 + w * 16) * 16;
    u32 aq[4];
    aq[0] = *(const u32*)(qp + gid * 16 + tig * 2);
    aq[1] = *(const u32*)(qp + (gid + 8) * 16 + tig * 2);
    aq[2] = *(const u32*)(qp + gid * 16 + tig * 2 + 8);
    aq[3] = *(const u32*)(qp + (gid + 8) * 16 + tig * 2 + 8);
    __syncthreads();

    float4 o0 = make_float4(0.f, 0.f, 0.f, 0.f);
    float4 o1 = make_float4(0.f, 0.f, 0.f, 0.f);
    u64 l2a = 0ull, l2b = 0ull;

    const u32* kaw = (const u32*)Ka;
    const u32* kbw = (const u32*)Kb;
    const u32* vw  = (const u32*)Vt;

#pragma unroll 2
    for (int n0 = 0; n0 < NPIX; n0 += 16) {
        u32 kb00 = kaw[(n0 + gid) * 4 + tig];
        u32 kb01 = kbw[(n0 + gid) * 4 + tig];
        u32 kb10 = kaw[(n0 + 8 + gid) * 4 + tig];
        u32 kb11 = kbw[(n0 + 8 + gid) * 4 + tig];
        float4 s0 = make_float4(0.f, 0.f, 0.f, 0.f);
        float4 s1 = make_float4(0.f, 0.f, 0.f, 0.f);
        mma16816(s0, aq, kb00, kb01);
        mma16816(s1, aq, kb10, kb11);

        u64 e0 = exp_dual(pack2(s0.x, s0.y));
        u64 e1 = exp_dual(pack2(s0.z, s0.w));
        u64 e2 = exp_dual(pack2(s1.x, s1.y));
        u64 e3 = exp_dual(pack2(s1.z, s1.w));
        l2a = fma2(e0, ONE, l2a); l2a = fma2(e2, ONE, l2a);
        l2b = fma2(e1, ONE, l2b); l2b = fma2(e3, ONE, l2b);

        // P fragments: hi only (verified R12/R13)
        float2 f0 = unpack2(e0), f1 = unpack2(e1), f2 = unpack2(e2), f3 = unpack2(e3);
        u32 ph[4] = {h2u(__floats2half2_rn(f0.x, f0.y)),
                     h2u(__floats2half2_rn(f1.x, f1.y)),
                     h2u(__floats2half2_rn(f2.x, f2.y)),
                     h2u(__floats2half2_rn(f3.x, f3.y))};

        u32 vb00 = vw[gid * 516 + (n0 >> 1) + tig];
        u32 vb01 = vw[gid * 516 + (n0 >> 1) + tig + 4];
        u32 vb10 = vw[(gid + 8) * 516 + (n0 >> 1) + tig];
        u32 vb11 = vw[(gid + 8) * 516 + (n0 >> 1) + tig + 4];

        mma16816(o0, ph, vb00, vb01);
        mma16816(o1, ph, vb10, vb11);
    }

    float2 lA = unpack2(l2a), lB = unpack2(l2b);
    float lr0 = lA.x + lA.y;
    float lr8 = lB.x + lB.y;
    lr0 += __shfl_xor_sync(0xFFFFFFFFu, lr0, 1);
    lr0 += __shfl_xor_sync(0xFFFFFFFFu, lr0, 2);
    lr8 += __shfl_xor_sync(0xFFFFFFFFu, lr8, 1);
    lr8 += __shfl_xor_sync(0xFFFFFFFFu, lr8, 2);
    float i0 = 1.0f / lr0, i8 = 1.0f / lr8;

    const int b = bh >> 3, h = bh & 7;
    float* ob = g_attn + b * (128 * NPIX) + h * (16 * NPIX);
    const int seq0 = qb * 128 + w * 16 + gid;
    const int d0 = tig * 2;
    ob[(d0 + 0) * NPIX + seq0]     = o0.x * i0;
    ob[(d0 + 1) * NPIX + seq0]     = o0.y * i0;
    ob[(d0 + 0) * NPIX + seq0 + 8] = o0.z * i8;
    ob[(d0 + 1) * NPIX + seq0 + 8] = o0.w * i8;
    ob[(d0 + 8) * NPIX + seq0]     = o1.x * i0;
    ob[(d0 + 9) * NPIX + seq0]     = o1.y * i0;
    ob[(d0 + 8) * NPIX + seq0 + 8] = o1.z * i8;
    ob[(d0 + 9) * NPIX + seq0 + 8] = o1.w * i8;
}

// ---------------- kernel 3: attn output projection (unchanged, FFMA2) ------
__global__ __launch_bounds__(256, 2) void k_attnproj(
    const float* __restrict__ w_attn, const float* __restrict__ b_attn,
    float* __restrict__ out)
{
    __shared__ float As[16][128];
    __shared__ float Bs[16][128];
    const int b  = blockIdx.z;
    const int n0 = blockIdx.x * 128;
    const int tid = threadIdx.x;
    const int tx = tid & 15;
    const int ty = tid >> 4;
    const float* Bsrc = g_attn + b * (128 * NPIX);

    const int a_ml0 = tid & 127, a_kq0 = (tid >> 7);
    const int b_kl0 = tid >> 5, b_nl0 = (tid & 31) * 4;

    float4 ar[2], br[2];
    ar[0] = *(const float4*)&w_attn[a_ml0 * 128 + a_kq0 * 4];
    ar[1] = *(const float4*)&w_attn[a_ml0 * 128 + (a_kq0 + 2) * 4];
    br[0] = *(const float4*)&Bsrc[b_kl0 * NPIX + n0 + b_nl0];
    br[1] = *(const float4*)&Bsrc[(b_kl0 + 8) * NPIX + n0 + b_nl0];

    u64 acc[8][4];
#pragma unroll
    for (int i = 0; i < 8; ++i)
#pragma unroll
        for (int j = 0; j < 4; ++j) acc[i][j] = 0ull;

    for (int c = 0; c < 8; ++c) {
        __syncthreads();
#pragma unroll
        for (int r = 0; r < 2; ++r) {
            int kq = a_kq0 + r * 2;
            As[kq * 4 + 0][a_ml0] = ((float*)&ar[r])[0];
            As[kq * 4 + 1][a_ml0] = ((float*)&ar[r])[1];
            As[kq * 4 + 2][a_ml0] = ((float*)&ar[r])[2];
            As[kq * 4 + 3][a_ml0] = ((float*)&ar[r])[3];
        }
        *(float4*)&Bs[b_kl0][b_nl0]     = br[0];
        *(float4*)&Bs[b_kl0 + 8][b_nl0] = br[1];
        __syncthreads();
        if (c < 7) {
            int k0 = (c + 1) * 16;
            ar[0] = *(const float4*)&w_attn[a_ml0 * 128 + k0 + a_kq0 * 4];
            ar[1] = *(const float4*)&w_attn[a_ml0 * 128 + k0 + (a_kq0 + 2) * 4];
            br[0] = *(const float4*)&Bsrc[(k0 + b_kl0) * NPIX + n0 + b_nl0];
            br[1] = *(const float4*)&Bsrc[(k0 + b_kl0 + 8) * NPIX + n0 + b_nl0];
        }
#pragma unroll
        for (int kk = 0; kk < 16; ++kk) {
            float4 a0 = *(const float4*)&As[kk][ty * 8];
            float4 a1 = *(const float4*)&As[kk][ty * 8 + 4];
            ulonglong2 b01 = *(const ulonglong2*)&Bs[kk][tx * 8];
            ulonglong2 b23 = *(const ulonglong2*)&Bs[kk][tx * 8 + 4];
            u64 bp[4] = {b01.x, b01.y, b23.x, b23.y};
            float am[8] = {a0.x, a0.y, a0.z, a0.w, a1.x, a1.y, a1.z, a1.w};
#pragma unroll
            for (int i = 0; i < 8; ++i) {
                u64 ad = pack2(am[i], am[i]);
#pragma unroll
                for (int j = 0; j < 4; ++j)
                    acc[i][j] = fma2(ad, bp[j], acc[i][j]);
            }
        }
    }

#pragma unroll
    for (int i = 0; i < 8; ++i) {
        int m = ty * 8 + i;
        float bias = b_attn[m];
        float v[8];
#pragma unroll
        for (int j = 0; j < 4; ++j) {
            float2 t = unpack2(acc[i][j]);
            v[j * 2 + 0] = t.x + bias;
            v[j * 2 + 1] = t.y + bias;
        }
        float* dst = out + b * 262144 + (128 + m) * NPIX + n0 + tx * 8;
        *(float4*)dst       = make_float4(v[0], v[1], v[2], v[3]);
        *(float4*)(dst + 4) = make_float4(v[4], v[5], v[6], v[7]);
    }
}

// ---------------- launch ----------------------------------------------------
extern "C" void kernel_launch(void* const* d_in, const int* in_sizes, int n_in,
                              void* d_out, int out_size)
{
    const float* x      = (const float*)d_in[0];
    const float* w_qkv  = (const float*)d_in[1];
    const float* b_qkv  = (const float*)d_in[2];
    const float* w_attn = (const float*)d_in[3];
    const float* b_attn = (const float*)d_in[4];
    const float* w_out  = (const float*)d_in[5];
    const float* b_out  = (const float*)d_in[6];
    float* out = (float*)d_out;

    k_cvt_w<<<512, 64>>>(w_qkv, w_out);
    dim3 gc(64, 32);
    k_cvt_x<<<gc, 256>>>(x);

    dim3 g1(8, 4, 32);                 // n-tiles(128), m-tiles(q/k/v/conv), batch
    k_proj<<<g1, 256>>>(b_qkv, b_out, out);

    const int smem_attn = (1024 * 16 + 16 * VROW) * (int)sizeof(__half); // 65792
    cudaFuncSetAttribute(k_attn, cudaFuncAttributeMaxDynamicSharedMemorySize,
                         smem_attn);
    dim3 g2(8, 256);                   // q-blocks x (b,h)
    k_attn<<<g2, 256, smem_attn>>>();

    dim3 g3(8, 1, 32);
    k_attnproj<<<g3, 256>>>(w_attn, b_attn, out);
}

// round 15
// speedup vs baseline: 2.1435x; 1.0861x over previous
#include <cuda_runtime.h>
#include <cuda_fp16.h>

// ---------------- problem constants ----------------
// B=32, CIN=256, H=W=32 (N=1024), DK=DV=128, HEADS=8, DKH=DVH=16, OUT=256
#define NB    32
#define NPIX  1024
#define NCIN  256

typedef unsigned long long u64;
typedef unsigned int u32;

// ---------------- scratch (static device mem; no allocations allowed) ------
__device__ __half g_qh[32 * 8 * 1024 * 16];   // [bh][n][16]  (pre-scaled 0.25)
__device__ __half g_kh[32 * 8 * 1024 * 16];   // [bh][n][16]
__device__ __half g_vt[32 * 8 * 16 * 1024];   // [bh][d][n]   (transposed)
__device__ __half g_attn_h[32 * 1024 * 128];  // [b][n][dv]   fp16 attn out
// pre-converted fp16 operands (chunk-major for coalesced staging)
__device__ __half g_wh[4 * 16 * 128 * 16];    // [mt][cs][128m][16k]  qkv/conv w hi
__device__ __half g_wl[4 * 16 * 128 * 16];    // qkv/conv w lo
__device__ __half g_xh[32 * 16 * 1024 * 16];  // [b][cs][1024n][16k]  x hi only
__device__ __half g_wah[8 * 128 * 16];        // [cs][128m][16k] w_attn hi
__device__ __half g_wal[8 * 128 * 16];        // w_attn lo

// ---------------- packed f32x2 helpers -------------------------------------
__device__ __forceinline__ u64 fma2(u64 a, u64 b, u64 c) {
    u64 d;
    asm("fma.rn.f32x2 %0, %1, %2, %3;" : "=l"(d) : "l"(a), "l"(b), "l"(c));
    return d;
}
__device__ __forceinline__ u64 pack2(float lo, float hi) {
    u64 d;
    asm("mov.b64 %0, {%1, %2};" : "=l"(d) : "f"(lo), "f"(hi));
    return d;
}
__device__ __forceinline__ float2 unpack2(u64 v) {
    float2 r;
    asm("mov.b64 {%0, %1}, %2;" : "=f"(r.x), "=f"(r.y) : "l"(v));
    return r;
}
__device__ __forceinline__ void split64(u64 v, u32& lo, u32& hi) {
    asm("mov.b64 {%0, %1}, %2;" : "=r"(lo), "=r"(hi) : "l"(v));
}
__device__ __forceinline__ u64 join64(u32 lo, u32 hi) {
    u64 d;
    asm("mov.b64 %0, {%1, %2};" : "=l"(d) : "r"(lo), "r"(hi));
    return d;
}
__device__ __forceinline__ u64 make2(float v) { return pack2(v, v); }
__device__ __forceinline__ u32 h2u(__half2 h) {
    union { __half2 h; u32 u; } c; c.h = h; return c.u;
}

// ---------------- dual packed exp, 6 fma2 + ALU bits-add (R14-verified) ----
__device__ __forceinline__ u64 exp_dual(u64 s2) {
    const u64 NEG1  = make2(-1.0f);
    const u64 L2E   = make2(1.4426950408889634f);
    const u64 MAGIC = make2(12582912.0f);            // 2^23 + 2^22
    const u64 C3 = make2(5.5504109e-2f);
    const u64 C2 = make2(2.4263210e-1f);             // economized
    const u64 C1 = make2(6.9314718e-1f);
    const u64 C0 = make2(9.9992490e-1f);
    u64 r  = fma2(s2, L2E, MAGIC);
    u64 mr = fma2(r, NEG1, MAGIC);
    u64 f  = fma2(s2, L2E, mr);
    u64 p  = fma2(C3, f, C2);
    p = fma2(p, f, C1);
    p = fma2(p, f, C0);
    u32 rl, rh, pl, ph;
    split64(r, rl, rh);
    split64(p, pl, ph);
    return join64(pl + (rl << 23), ph + (rh << 23));
}

// ---------------- mma.sync m16n8k16 fp16 -> fp32 ---------------------------
__device__ __forceinline__ void mma16816(float4& c, const u32* a, u32 b0, u32 b1) {
    asm volatile(
        "mma.sync.aligned.m16n8k16.row.col.f32.f16.f16.f32 "
        "{%0,%1,%2,%3}, {%4,%5,%6,%7}, {%8,%9}, {%0,%1,%2,%3};"
        : "+f"(c.x), "+f"(c.y), "+f"(c.z), "+f"(c.w)
        : "r"(a[0]), "r"(a[1]), "r"(a[2]), "r"(a[3]), "r"(b0), "r"(b1));
}

__device__ __forceinline__ void hsplit(float v, __half& hi, __half& lo) {
    hi = __float2half_rn(v);
    lo = __float2half_rn(v - __half2float(hi));
}

// ---------------- pre-pass: convert qkv/conv weights hi/lo chunk-major -----
__global__ void k_cvt_w(const float* __restrict__ w_qkv,
                        const float* __restrict__ w_out)
{
    const int m = blockIdx.x;
    const int k0 = threadIdx.x * 4;
    const float* src = (m < 384) ? &w_qkv[m * NCIN + k0]
                                 : &w_out[(m - 384) * NCIN + k0];
    const float sc = (m < 128) ? 0.25f : 1.0f;
    float4 v = *(const float4*)src;
    __half h[4], l[4];
    hsplit(v.x * sc, h[0], l[0]);
    hsplit(v.y * sc, h[1], l[1]);
    hsplit(v.z * sc, h[2], l[2]);
    hsplit(v.w * sc, h[3], l[3]);
    const int mt = m >> 7, ml = m & 127, cs = k0 >> 4, ko = k0 & 15;
    const int dst = ((mt * 16 + cs) * 128 + ml) * 16 + ko;
    *(uint2*)&g_wh[dst] = *(uint2*)h;
    *(uint2*)&g_wl[dst] = *(uint2*)l;
}

// ---------------- pre-pass: convert w_attn hi/lo chunk-major ---------------
__global__ void k_cvt_wa(const float* __restrict__ w_attn)
{
    const int m = blockIdx.x;            // 0..127
    const int k0 = threadIdx.x * 4;      // 0..124
    float4 v = *(const float4*)&w_attn[m * 128 + k0];
    __half h[4], l[4];
    hsplit(v.x, h[0], l[0]);
    hsplit(v.y, h[1], l[1]);
    hsplit(v.z, h[2], l[2]);
    hsplit(v.w, h[3], l[3]);
    const int cs = k0 >> 4, ko = k0 & 15;
    const int dst = (cs * 128 + m) * 16 + ko;
    *(uint2*)&g_wah[dst] = *(uint2*)h;
    *(uint2*)&g_wal[dst] = *(uint2*)l;
}

// ---------------- pre-pass: transpose+convert x to fp16 hi chunk-major -----
__global__ __launch_bounds__(256) void k_cvt_x(const float* __restrict__ x)
{
    __shared__ float tile[16][260];
    const int cc = blockIdx.x >> 2;
    const int ng = blockIdx.x & 3;
    const int b  = blockIdx.y;
    const int tid = threadIdx.x;
#pragma unroll
    for (int i = 0; i < 4; ++i) {
        int idx = tid + i * 256;
        int r = idx >> 6, c4 = (idx & 63) * 4;
        float4 v = *(const float4*)&x[b * (NCIN * NPIX) + (cc * 16 + r) * NPIX
                                      + ng * 256 + c4];
        tile[r][c4 + 0] = v.x; tile[r][c4 + 1] = v.y;
        tile[r][c4 + 2] = v.z; tile[r][c4 + 3] = v.w;
    }
    __syncthreads();
    __half h[16];
#pragma unroll
    for (int k = 0; k < 16; ++k) h[k] = __float2half_rn(tile[k][tid]);
    const int dst = ((b * 16 + cc) * 1024 + ng * 256 + tid) * 16;
    *(uint4*)&g_xh[dst]     = *(uint4*)&h[0];
    *(uint4*)&g_xh[dst + 8] = *(uint4*)&h[8];
}

// ---------------- kernel 1: tensor-core fused projection (R14-verified) ----
#define SSTR 132
__global__ __launch_bounds__(256, 2) void k_proj(
    const float* __restrict__ b_qkv, const float* __restrict__ b_out,
    float* __restrict__ out)
{
    __shared__ __align__(16) char smraw[24576];
    __half* sAh = (__half*)smraw;            // [128 m][24]
    __half* sAl = (__half*)smraw + 3072;
    __half* sBh = (__half*)smraw + 6144;     // [128 n][24]
    float*  S   = (float*)smraw;             // epilogue alias [32][SSTR]

    const int b  = blockIdx.z;
    const int mt = blockIdx.y;               // 0=q 1=k 2=v 3=conv
    const int n0 = blockIdx.x * 128;
    const int tid = threadIdx.x;
    const int w    = tid >> 5;
    const int lane = tid & 31;
    const int gid = lane >> 2, tig = lane & 3;
    const int wm = w & 3;
    const int wn = w >> 2;

    const int sm_row = tid >> 1;
    const int sm_hp  = tid & 1;

    const __half* wsrch = g_wh + (mt * 16) * 128 * 16;
    const __half* wsrcl = g_wl + (mt * 16) * 128 * 16;
    const __half* xsrch = g_xh + ((u64)b * 16) * 1024 * 16;
    const int aoff = sm_row * 16 + sm_hp * 8;
    const int boff = (n0 + sm_row) * 16 + sm_hp * 8;

    uint4 pah, pal, pbh;
    pah = *(const uint4*)&wsrch[aoff];
    pal = *(const uint4*)&wsrcl[aoff];
    pbh = *(const uint4*)&xsrch[boff];

    float4 c[2][8];
#pragma unroll
    for (int t = 0; t < 2; ++t)
#pragma unroll
        for (int nb = 0; nb < 8; ++nb) c[t][nb] = make_float4(0.f, 0.f, 0.f, 0.f);

    for (int cs = 0; cs < 16; ++cs) {
        __syncthreads();
        *(uint4*)&sAh[sm_row * 24 + sm_hp * 8] = pah;
        *(uint4*)&sAl[sm_row * 24 + sm_hp * 8] = pal;
        *(uint4*)&sBh[sm_row * 24 + sm_hp * 8] = pbh;
        __syncthreads();
        if (cs < 15) {
            const int anext = (cs + 1) * 128 * 16 + aoff;
            const int bnext = (cs + 1) * 1024 * 16 + boff;
            pah = *(const uint4*)&wsrch[anext];
            pal = *(const uint4*)&wsrcl[anext];
            pbh = *(const uint4*)&xsrch[bnext];
        }

        const u32* Ahw = (const u32*)sAh;
        const u32* Alw = (const u32*)sAl;
        const u32* Bhw = (const u32*)sBh;

        u32 ah[2][4], al[2][4];
#pragma unroll
        for (int t = 0; t < 2; ++t) {
            int r0 = wm * 32 + t * 16 + gid;
            ah[t][0] = Ahw[r0 * 12 + tig];
            ah[t][1] = Ahw[(r0 + 8) * 12 + tig];
            ah[t][2] = Ahw[r0 * 12 + tig + 4];
            ah[t][3] = Ahw[(r0 + 8) * 12 + tig + 4];
            al[t][0] = Alw[r0 * 12 + tig];
            al[t][1] = Alw[(r0 + 8) * 12 + tig];
            al[t][2] = Alw[r0 * 12 + tig + 4];
            al[t][3] = Alw[(r0 + 8) * 12 + tig + 4];
        }
        u32 bf[8][2];
#pragma unroll
        for (int nb = 0; nb < 8; ++nb) {
            int n = wn * 64 + nb * 8 + gid;
            bf[nb][0] = Bhw[n * 12 + tig];
            bf[nb][1] = Bhw[n * 12 + tig + 4];
        }
#pragma unroll
        for (int nb = 0; nb < 8; ++nb) {
            mma16816(c[0][nb], ah[0], bf[nb][0], bf[nb][1]);
            mma16816(c[1][nb], ah[1], bf[nb][0], bf[nb][1]);
            mma16816(c[0][nb], al[0], bf[nb][0], bf[nb][1]);
            mma16816(c[1][nb], al[1], bf[nb][0], bf[nb][1]);
        }
    }

    const float wscale = (mt == 0) ? 0.25f : 1.0f;
    float bias[2][2];
#pragma unroll
    for (int t = 0; t < 2; ++t) {
        int m = wm * 32 + t * 16 + gid;
        if (mt < 3) {
            bias[t][0] = b_qkv[mt * 128 + m] * wscale;
            bias[t][1] = b_qkv[mt * 128 + m + 8] * wscale;
        } else {
            bias[t][0] = b_out[m];
            bias[t][1] = b_out[m + 8];
        }
    }
#pragma unroll
    for (int t = 0; t < 2; ++t)
#pragma unroll
        for (int nb = 0; nb < 8; ++nb) {
            c[t][nb].x += bias[t][0]; c[t][nb].y += bias[t][0];
            c[t][nb].z += bias[t][1]; c[t][nb].w += bias[t][1];
        }

    for (int mc = 0; mc < 4; ++mc) {
        __syncthreads();
        if (wm == mc) {
#pragma unroll
            for (int t = 0; t < 2; ++t)
#pragma unroll
                for (int nb = 0; nb < 8; ++nb) {
                    int col = wn * 64 + nb * 8 + tig * 2;
                    int r0 = t * 16 + gid;
                    *(float2*)&S[r0 * SSTR + col]       = make_float2(c[t][nb].x, c[t][nb].y);
                    *(float2*)&S[(r0 + 8) * SSTR + col] = make_float2(c[t][nb].z, c[t][nb].w);
                }
        }
        __syncthreads();

        if (mt == 3) {
#pragma unroll
            for (int t = 0; t < 4; ++t) {
                int idx = tid + t * 256;
                int nq = idx & 31, row = idx >> 5;
                float4 v = *(const float4*)&S[row * SSTR + nq * 4];
                *(float4*)&out[b * 262144 + (mc * 32 + row) * NPIX + n0 + nq * 4] = v;
            }
        } else if (mt == 2) {
#pragma unroll
            for (int t = 0; t < 2; ++t) {
                int idx = tid + t * 256;
                int noct = idx & 15, row = idx >> 4;
                const float* sp = &S[row * SSTR + noct * 8];
                uint4 u;
                u.x = h2u(__floats2half2_rn(sp[0], sp[1]));
                u.y = h2u(__floats2half2_rn(sp[2], sp[3]));
                u.z = h2u(__floats2half2_rn(sp[4], sp[5]));
                u.w = h2u(__floats2half2_rn(sp[6], sp[7]));
                int h = mc * 2 + (row >> 4);
                int d = row & 15;
                *(uint4*)&g_vt[(((b * 8 + h) * 16 + d) << 10) + n0 + noct * 8] = u;
            }
        } else {
            __half* g = (mt == 0) ? g_qh : g_kh;
#pragma unroll
            for (int t = 0; t < 2; ++t) {
                int idx = tid + t * 256;
                int n = idx & 127;
                int rest = idx >> 7;
                int hsel = rest >> 1, dh = rest & 1;
                int rb = hsel * 16 + dh * 8;
                uint4 u;
                u.x = h2u(__floats2half2_rn(S[(rb + 0) * SSTR + n], S[(rb + 1) * SSTR + n]));
                u.y = h2u(__floats2half2_rn(S[(rb + 2) * SSTR + n], S[(rb + 3) * SSTR + n]));
                u.z = h2u(__floats2half2_rn(S[(rb + 4) * SSTR + n], S[(rb + 5) * SSTR + n]));
                u.w = h2u(__floats2half2_rn(S[(rb + 6) * SSTR + n], S[(rb + 7) * SSTR + n]));
                int bh = b * 8 + mc * 2 + hsel;
                *(uint4*)&g[((u64)bh << 14) + (u64)(n0 + n) * 16 + dh * 8] = u;
            }
        }
    }
}

// ---------------- kernel 2: tensor-core attention (fp16 [n][dv] output) ----
#define VROW 1032     // halves per Vt row (516 words)
__global__ __launch_bounds__(256, 3) void k_attn()
{
    extern __shared__ __half sm[];
    __half* Ka = sm;                    // [1024][8]  k dims 0..7
    __half* Kb = sm + 8192;             // [1024][8]  k dims 8..15
    __half* Vt = sm + 16384;            // [16][VROW]
    const int qb  = blockIdx.x;
    const int bh  = blockIdx.y;
    const int tid = threadIdx.x;
    const int w   = tid >> 5;
    const int lane = tid & 31;
    const int gid = lane >> 2, tig = lane & 3;
    const u64 ONE = make2(1.0f);

    const uint4* ksrc = (const uint4*)(g_kh + ((u64)bh << 14));
    const uint4* vsrc = (const uint4*)(g_vt + ((u64)bh << 14));
#pragma unroll
    for (int j = 0; j < 8; ++j) {
        int idx = tid + j * 256;
        int seq = idx >> 1, hp = idx & 1;
        __half* kd = hp ? Kb : Ka;
        *(uint4*)&kd[seq * 8] = ksrc[idx];
    }
#pragma unroll
    for (int j = 0; j < 8; ++j) {
        int idx = tid + j * 256;
        int row = idx >> 7, off = (idx & 127) * 8;
        *(uint4*)&Vt[row * VROW + off] = vsrc[idx];
    }

    const __half* qp = g_qh + ((u64)bh << 14) + (qb * 128 + w * 16) * 16;
    u32 aq[4];
    aq[0] = *(const u32*)(qp + gid * 16 + tig * 2);
    aq[1] = *(const u32*)(qp + (gid + 8) * 16 + tig * 2);
    aq[2] = *(const u32*)(qp + gid * 16 + tig * 2 + 8);
    aq[3] = *(const u32*)(qp + (gid + 8) * 16 + tig * 2 + 8);
    __syncthreads();

    float4 o0 = make_float4(0.f, 0.f, 0.f, 0.f);
    float4 o1 = make_float4(0.f, 0.f, 0.f, 0.f);
    u64 l2a = 0ull, l2b = 0ull;

    const u32* kaw = (const u32*)Ka;
    const u32* kbw = (const u32*)Kb;
    const u32* vw  = (const u32*)Vt;

#pragma unroll 2
    for (int n0 = 0; n0 < NPIX; n0 += 16) {
        u32 kb00 = kaw[(n0 + gid) * 4 + tig];
        u32 kb01 = kbw[(n0 + gid) * 4 + tig];
        u32 kb10 = kaw[(n0 + 8 + gid) * 4 + tig];
        u32 kb11 = kbw[(n0 + 8 + gid) * 4 + tig];
        float4 s0 = make_float4(0.f, 0.f, 0.f, 0.f);
        float4 s1 = make_float4(0.f, 0.f, 0.f, 0.f);
        mma16816(s0, aq, kb00, kb01);
        mma16816(s1, aq, kb10, kb11);

        u64 e0 = exp_dual(pack2(s0.x, s0.y));
        u64 e1 = exp_dual(pack2(s0.z, s0.w));
        u64 e2 = exp_dual(pack2(s1.x, s1.y));
        u64 e3 = exp_dual(pack2(s1.z, s1.w));
        l2a = fma2(e0, ONE, l2a); l2a = fma2(e2, ONE, l2a);
        l2b = fma2(e1, ONE, l2b); l2b = fma2(e3, ONE, l2b);

        float2 f0 = unpack2(e0), f1 = unpack2(e1), f2 = unpack2(e2), f3 = unpack2(e3);
        u32 ph[4] = {h2u(__floats2half2_rn(f0.x, f0.y)),
                     h2u(__floats2half2_rn(f1.x, f1.y)),
                     h2u(__floats2half2_rn(f2.x, f2.y)),
                     h2u(__floats2half2_rn(f3.x, f3.y))};

        u32 vb00 = vw[gid * 516 + (n0 >> 1) + tig];
        u32 vb01 = vw[gid * 516 + (n0 >> 1) + tig + 4];
        u32 vb10 = vw[(gid + 8) * 516 + (n0 >> 1) + tig];
        u32 vb11 = vw[(gid + 8) * 516 + (n0 >> 1) + tig + 4];

        mma16816(o0, ph, vb00, vb01);
        mma16816(o1, ph, vb10, vb11);
    }

    float2 lA = unpack2(l2a), lB = unpack2(l2b);
    float lr0 = lA.x + lA.y;
    float lr8 = lB.x + lB.y;
    lr0 += __shfl_xor_sync(0xFFFFFFFFu, lr0, 1);
    lr0 += __shfl_xor_sync(0xFFFFFFFFu, lr0, 2);
    lr8 += __shfl_xor_sync(0xFFFFFFFFu, lr8, 1);
    lr8 += __shfl_xor_sync(0xFFFFFFFFu, lr8, 2);
    float i0 = 1.0f / lr0, i8 = 1.0f / lr8;

    // fp16 output, [b][n][dv] layout (dv = h*16 + d) — 4 x 4B stores
    const int b = bh >> 3, h = bh & 7;
    __half* ob = g_attn_h + (u64)b * (NPIX * 128);
    const int seq0 = qb * 128 + w * 16 + gid;
    const int d0 = h * 16 + tig * 2;
    *(u32*)&ob[(u64)seq0 * 128 + d0]           = h2u(__floats2half2_rn(o0.x * i0, o0.y * i0));
    *(u32*)&ob[(u64)seq0 * 128 + d0 + 8]       = h2u(__floats2half2_rn(o1.x * i0, o1.y * i0));
    *(u32*)&ob[(u64)(seq0 + 8) * 128 + d0]     = h2u(__floats2half2_rn(o0.z * i8, o0.w * i8));
    *(u32*)&ob[(u64)(seq0 + 8) * 128 + d0 + 8] = h2u(__floats2half2_rn(o1.z * i8, o1.w * i8));
}

// ---------------- kernel 3: attn output projection on tensor cores ---------
// C[128m x 128n] = w_attn[128m x 128k (hi/lo)] * attn[128k x 128n (fp16)].
// Same skeleton as k_proj with 8 K-chunks; epilogue -> out channels 128..255.
__global__ __launch_bounds__(256, 2) void k_attnproj(
    const float* __restrict__ b_attn, float* __restrict__ out)
{
    __shared__ __align__(16) char smraw[24576];
    __half* sAh = (__half*)smraw;            // [128 m][24]
    __half* sAl = (__half*)smraw + 3072;
    __half* sBh = (__half*)smraw + 6144;     // [128 n][24]
    float*  S   = (float*)smraw;             // epilogue alias [32][SSTR]

    const int b  = blockIdx.z;
    const int n0 = blockIdx.x * 128;
    const int tid = threadIdx.x;
    const int w    = tid >> 5;
    const int lane = tid & 31;
    const int gid = lane >> 2, tig = lane & 3;
    const int wm = w & 3;
    const int wn = w >> 2;

    const int sm_row = tid >> 1;
    const int sm_hp  = tid & 1;

    const __half* asrc = g_attn_h + (u64)b * (NPIX * 128);
    const int aoff = sm_row * 16 + sm_hp * 8;                 // into g_wah/g_wal chunk
    const u64 boff = (u64)(n0 + sm_row) * 128 + sm_hp * 8;    // into attn row

    uint4 pah, pal, pbh;
    pah = *(const uint4*)&g_wah[aoff];
    pal = *(const uint4*)&g_wal[aoff];
    pbh = *(const uint4*)&asrc[boff];

    float4 c[2][8];
#pragma unroll
    for (int t = 0; t < 2; ++t)
#pragma unroll
        for (int nb = 0; nb < 8; ++nb) c[t][nb] = make_float4(0.f, 0.f, 0.f, 0.f);

    for (int cs = 0; cs < 8; ++cs) {
        __syncthreads();
        *(uint4*)&sAh[sm_row * 24 + sm_hp * 8] = pah;
        *(uint4*)&sAl[sm_row * 24 + sm_hp * 8] = pal;
        *(uint4*)&sBh[sm_row * 24 + sm_hp * 8] = pbh;
        __syncthreads();
        if (cs < 7) {
            pah = *(const uint4*)&g_wah[(cs + 1) * 128 * 16 + aoff];
            pal = *(const uint4*)&g_wal[(cs + 1) * 128 * 16 + aoff];
            pbh = *(const uint4*)&asrc[boff + (cs + 1) * 16];
        }

        const u32* Ahw = (const u32*)sAh;
        const u32* Alw = (const u32*)sAl;
        const u32* Bhw = (const u32*)sBh;

        u32 ah[2][4], al[2][4];
#pragma unroll
        for (int t = 0; t < 2; ++t) {
            int r0 = wm * 32 + t * 16 + gid;
            ah[t][0] = Ahw[r0 * 12 + tig];
            ah[t][1] = Ahw[(r0 + 8) * 12 + tig];
            ah[t][2] = Ahw[r0 * 12 + tig + 4];
            ah[t][3] = Ahw[(r0 + 8) * 12 + tig + 4];
            al[t][0] = Alw[r0 * 12 + tig];
            al[t][1] = Alw[(r0 + 8) * 12 + tig];
            al[t][2] = Alw[r0 * 12 + tig + 4];
            al[t][3] = Alw[(r0 + 8) * 12 + tig + 4];
        }
        u32 bf[8][2];
#pragma unroll
        for (int nb = 0; nb < 8; ++nb) {
            int n = wn * 64 + nb * 8 + gid;
            bf[nb][0] = Bhw[n * 12 + tig];
            bf[nb][1] = Bhw[n * 12 + tig + 4];
        }
#pragma unroll
        for (int nb = 0; nb < 8; ++nb) {
            mma16816(c[0][nb], ah[0], bf[nb][0], bf[nb][1]);
            mma16816(c[1][nb], ah[1], bf[nb][0], bf[nb][1]);
            mma16816(c[0][nb], al[0], bf[nb][0], bf[nb][1]);
            mma16816(c[1][nb], al[1], bf[nb][0], bf[nb][1]);
        }
    }

    float bias[2][2];
#pragma unroll
    for (int t = 0; t < 2; ++t) {
        int m = wm * 32 + t * 16 + gid;
        bias[t][0] = b_attn[m];
        bias[t][1] = b_attn[m + 8];
    }
#pragma unroll
    for (int t = 0; t < 2; ++t)
#pragma unroll
        for (int nb = 0; nb < 8; ++nb) {
            c[t][nb].x += bias[t][0]; c[t][nb].y += bias[t][0];
            c[t][nb].z += bias[t][1]; c[t][nb].w += bias[t][1];
        }

    for (int mc = 0; mc < 4; ++mc) {
        __syncthreads();
        if (wm == mc) {
#pragma unroll
            for (int t = 0; t < 2; ++t)
#pragma unroll
                for (int nb = 0; nb < 8; ++nb) {
                    int col = wn * 64 + nb * 8 + tig * 2;
                    int r0 = t * 16 + gid;
                    *(float2*)&S[r0 * SSTR + col]       = make_float2(c[t][nb].x, c[t][nb].y);
                    *(float2*)&S[(r0 + 8) * SSTR + col] = make_float2(c[t][nb].z, c[t][nb].w);
                }
        }
        __syncthreads();
#pragma unroll
        for (int t = 0; t < 4; ++t) {
            int idx = tid + t * 256;
            int nq = idx & 31, row = idx >> 5;
            float4 v = *(const float4*)&S[row * SSTR + nq * 4];
            *(float4*)&out[b * 262144 + (128 + mc * 32 + row) * NPIX + n0 + nq * 4] = v;
        }
    }
}

// ---------------- launch ----------------------------------------------------
extern "C" void kernel_launch(void* const* d_in, const int* in_sizes, int n_in,
                              void* d_out, int out_size)
{
    const float* x      = (const float*)d_in[0];
    const float* w_qkv  = (const float*)d_in[1];
    const float* b_qkv  = (const float*)d_in[2];
    const float* w_attn = (const float*)d_in[3];
    const float* b_attn = (const float*)d_in[4];
    const float* w_out  = (const float*)d_in[5];
    const float* b_out  = (const float*)d_in[6];
    float* out = (float*)d_out;

    k_cvt_w<<<512, 64>>>(w_qkv, w_out);
    k_cvt_wa<<<128, 32>>>(w_attn);
    dim3 gc(64, 32);
    k_cvt_x<<<gc, 256>>>(x);

    dim3 g1(8, 4, 32);                 // n-tiles(128), m-tiles(q/k/v/conv), batch
    k_proj<<<g1, 256>>>(b_qkv, b_out, out);

    const int smem_attn = (1024 * 16 + 16 * VROW) * (int)sizeof(__half); // 65792
    cudaFuncSetAttribute(k_attn, cudaFuncAttributeMaxDynamicSharedMemorySize,
                         smem_attn);
    dim3 g2(8, 256);                   // q-blocks x (b,h)
    k_attn<<<g2, 256, smem_attn>>>();

    dim3 g3(8, 1, 32);
    k_attnproj<<<g3, 256>>>(b_attn, out);
}

// round 17
// speedup vs baseline: 2.2170x; 1.0343x over previous
#include <cuda_runtime.h>
#include <cuda_fp16.h>

// ---------------- problem constants ----------------
// B=32, CIN=256, H=W=32 (N=1024), DK=DV=128, HEADS=8, DKH=DVH=16, OUT=256
#define NB    32
#define NPIX  1024
#define NCIN  256

typedef unsigned long long u64;
typedef unsigned int u32;

// ---------------- scratch (static device mem; no allocations allowed) ------
__device__ __half g_qh[32 * 8 * 1024 * 16];   // [bh][n][16]  (pre-scaled 0.25)
__device__ __half g_kh[32 * 8 * 1024 * 16];   // [bh][n][16]
__device__ __half g_vt[32 * 8 * 16 * 1024];   // [bh][d][n]   (transposed)
__device__ __half g_attn_h[32 * 1024 * 128];  // [b][n][dv]   fp16 attn out
// pre-converted fp16 operands (chunk-major for coalesced staging)
__device__ __half g_wh[4 * 16 * 128 * 16];    // [mt][cs][128m][16k]  qkv/conv w hi
__device__ __half g_wl[4 * 16 * 128 * 16];    // qkv/conv w lo
__device__ __half g_xh[32 * 16 * 1024 * 16];  // [b][cs][1024n][16k]  x hi only
__device__ __half g_wah[8 * 128 * 16];        // [cs][128m][16k] w_attn hi
__device__ __half g_wal[8 * 128 * 16];        // w_attn lo

// ---------------- packed f32x2 helpers -------------------------------------
__device__ __forceinline__ u64 fma2(u64 a, u64 b, u64 c) {
    u64 d;
    asm("fma.rn.f32x2 %0, %1, %2, %3;" : "=l"(d) : "l"(a), "l"(b), "l"(c));
    return d;
}
__device__ __forceinline__ u64 pack2(float lo, float hi) {
    u64 d;
    asm("mov.b64 %0, {%1, %2};" : "=l"(d) : "f"(lo), "f"(hi));
    return d;
}
__device__ __forceinline__ float2 unpack2(u64 v) {
    float2 r;
    asm("mov.b64 {%0, %1}, %2;" : "=f"(r.x), "=f"(r.y) : "l"(v));
    return r;
}
__device__ __forceinline__ void split64(u64 v, u32& lo, u32& hi) {
    asm("mov.b64 {%0, %1}, %2;" : "=r"(lo), "=r"(hi) : "l"(v));
}
__device__ __forceinline__ u64 join64(u32 lo, u32 hi) {
    u64 d;
    asm("mov.b64 %0, {%1, %2};" : "=l"(d) : "r"(lo), "r"(hi));
    return d;
}
__device__ __forceinline__ u64 make2(float v) { return pack2(v, v); }
__device__ __forceinline__ u32 h2u(__half2 h) {
    union { __half2 h; u32 u; } c; c.h = h; return c.u;
}

// ---------------- dual packed exp, 6 fma2 + ALU bits-add (R14-verified) ----
__device__ __forceinline__ u64 exp_dual(u64 s2) {
    const u64 NEG1  = make2(-1.0f);
    const u64 L2E   = make2(1.4426950408889634f);
    const u64 MAGIC = make2(12582912.0f);            // 2^23 + 2^22
    const u64 C3 = make2(5.5504109e-2f);
    const u64 C2 = make2(2.4263210e-1f);             // economized
    const u64 C1 = make2(6.9314718e-1f);
    const u64 C0 = make2(9.9992490e-1f);
    u64 r  = fma2(s2, L2E, MAGIC);
    u64 mr = fma2(r, NEG1, MAGIC);
    u64 f  = fma2(s2, L2E, mr);
    u64 p  = fma2(C3, f, C2);
    p = fma2(p, f, C1);
    p = fma2(p, f, C0);
    u32 rl, rh, pl, ph;
    split64(r, rl, rh);
    split64(p, pl, ph);
    return join64(pl + (rl << 23), ph + (rh << 23));
}

// ---------------- mma.sync m16n8k16 fp16 -> fp32 ---------------------------
__device__ __forceinline__ void mma16816(float4& c, const u32* a, u32 b0, u32 b1) {
    asm volatile(
        "mma.sync.aligned.m16n8k16.row.col.f32.f16.f16.f32 "
        "{%0,%1,%2,%3}, {%4,%5,%6,%7}, {%8,%9}, {%0,%1,%2,%3};"
        : "+f"(c.x), "+f"(c.y), "+f"(c.z), "+f"(c.w)
        : "r"(a[0]), "r"(a[1]), "r"(a[2]), "r"(a[3]), "r"(b0), "r"(b1));
}

__device__ __forceinline__ void hsplit(float v, __half& hi, __half& lo) {
    hi = __float2half_rn(v);
    lo = __float2half_rn(v - __half2float(hi));
}

// ---------------- pre-pass: convert qkv/conv weights hi/lo chunk-major -----
__global__ void k_cvt_w(const float* __restrict__ w_qkv,
                        const float* __restrict__ w_out)
{
    const int m = blockIdx.x;
    const int k0 = threadIdx.x * 4;
    const float* src = (m < 384) ? &w_qkv[m * NCIN + k0]
                                 : &w_out[(m - 384) * NCIN + k0];
    const float sc = (m < 128) ? 0.25f : 1.0f;
    float4 v = *(const float4*)src;
    __half h[4], l[4];
    hsplit(v.x * sc, h[0], l[0]);
    hsplit(v.y * sc, h[1], l[1]);
    hsplit(v.z * sc, h[2], l[2]);
    hsplit(v.w * sc, h[3], l[3]);
    const int mt = m >> 7, ml = m & 127, cs = k0 >> 4, ko = k0 & 15;
    const int dst = ((mt * 16 + cs) * 128 + ml) * 16 + ko;
    *(uint2*)&g_wh[dst] = *(uint2*)h;
    *(uint2*)&g_wl[dst] = *(uint2*)l;
}

// ---------------- pre-pass: convert w_attn hi/lo chunk-major ---------------
__global__ void k_cvt_wa(const float* __restrict__ w_attn)
{
    const int m = blockIdx.x;            // 0..127
    const int k0 = threadIdx.x * 4;      // 0..124
    float4 v = *(const float4*)&w_attn[m * 128 + k0];
    __half h[4], l[4];
    hsplit(v.x, h[0], l[0]);
    hsplit(v.y, h[1], l[1]);
    hsplit(v.z, h[2], l[2]);
    hsplit(v.w, h[3], l[3]);
    const int cs = k0 >> 4, ko = k0 & 15;
    const int dst = (cs * 128 + m) * 16 + ko;
    *(uint2*)&g_wah[dst] = *(uint2*)h;
    *(uint2*)&g_wal[dst] = *(uint2*)l;
}

// ---------------- pre-pass: transpose+convert x to fp16 hi chunk-major -----
__global__ __launch_bounds__(256) void k_cvt_x(const float* __restrict__ x)
{
    __shared__ float tile[16][260];
    const int cc = blockIdx.x >> 2;
    const int ng = blockIdx.x & 3;
    const int b  = blockIdx.y;
    const int tid = threadIdx.x;
#pragma unroll
    for (int i = 0; i < 4; ++i) {
        int idx = tid + i * 256;
        int r = idx >> 6, c4 = (idx & 63) * 4;
        float4 v = *(const float4*)&x[b * (NCIN * NPIX) + (cc * 16 + r) * NPIX
                                      + ng * 256 + c4];
        tile[r][c4 + 0] = v.x; tile[r][c4 + 1] = v.y;
        tile[r][c4 + 2] = v.z; tile[r][c4 + 3] = v.w;
    }
    __syncthreads();
    __half h[16];
#pragma unroll
    for (int k = 0; k < 16; ++k) h[k] = __float2half_rn(tile[k][tid]);
    const int dst = ((b * 16 + cc) * 1024 + ng * 256 + tid) * 16;
    *(uint4*)&g_xh[dst]     = *(uint4*)&h[0];
    *(uint4*)&g_xh[dst + 8] = *(uint4*)&h[8];
}

// ---------------- kernel 1: tensor-core fused projection -------------------
// Double-buffered staging (1 sync/chunk) + reordered MMAs (dep distance 16).
// BUFH = 3 regions x 3072 HALVES = 9216 halves/buffer (R16 had 4608: overlap bug).
#define SSTR 132
#define BUFH 9216
__global__ __launch_bounds__(256, 2) void k_proj(
    const float* __restrict__ b_qkv, const float* __restrict__ b_out,
    float* __restrict__ out)
{
    __shared__ __align__(16) char smraw[36864];
    __half* smh = (__half*)smraw;
    float*  S   = (float*)smraw;             // epilogue alias [32][SSTR]

    const int b  = blockIdx.z;
    const int mt = blockIdx.y;               // 0=q 1=k 2=v 3=conv
    const int n0 = blockIdx.x * 128;
    const int tid = threadIdx.x;
    const int w    = tid >> 5;
    const int lane = tid & 31;
    const int gid = lane >> 2, tig = lane & 3;
    const int wm = w & 3;
    const int wn = w >> 2;

    const int sm_row = tid >> 1;
    const int sm_hp  = tid & 1;
    const int soff = sm_row * 24 + sm_hp * 8;

    const __half* wsrch = g_wh + (mt * 16) * 128 * 16;
    const __half* wsrcl = g_wl + (mt * 16) * 128 * 16;
    const __half* xsrch = g_xh + ((u64)b * 16) * 1024 * 16;
    const int aoff = sm_row * 16 + sm_hp * 8;
    const int boff = (n0 + sm_row) * 16 + sm_hp * 8;

    // stage chunk 0 into buffer 0
    {
        uint4 pah = *(const uint4*)&wsrch[aoff];
        uint4 pal = *(const uint4*)&wsrcl[aoff];
        uint4 pbh = *(const uint4*)&xsrch[boff];
        *(uint4*)&smh[soff]        = pah;
        *(uint4*)&smh[3072 + soff] = pal;
        *(uint4*)&smh[6144 + soff] = pbh;
    }
    __syncthreads();

    float4 c[2][8];
#pragma unroll
    for (int t = 0; t < 2; ++t)
#pragma unroll
        for (int nb = 0; nb < 8; ++nb) c[t][nb] = make_float4(0.f, 0.f, 0.f, 0.f);

    for (int cs = 0; cs < 16; ++cs) {
        const int buf = cs & 1;
        uint4 pah, pal, pbh;
        if (cs < 15) {          // issue next-chunk loads early (overlap w/ MMA)
            const int anext = (cs + 1) * 128 * 16 + aoff;
            const int bnext = (cs + 1) * 1024 * 16 + boff;
            pah = *(const uint4*)&wsrch[anext];
            pal = *(const uint4*)&wsrcl[anext];
            pbh = *(const uint4*)&xsrch[bnext];
        }

        const u32* Ahw = (const u32*)(smh + buf * BUFH);
        const u32* Alw = (const u32*)(smh + buf * BUFH + 3072);
        const u32* Bhw = (const u32*)(smh + buf * BUFH + 6144);

        u32 ah[2][4], al[2][4];
#pragma unroll
        for (int t = 0; t < 2; ++t) {
            int r0 = wm * 32 + t * 16 + gid;
            ah[t][0] = Ahw[r0 * 12 + tig];
            ah[t][1] = Ahw[(r0 + 8) * 12 + tig];
            ah[t][2] = Ahw[r0 * 12 + tig + 4];
            ah[t][3] = Ahw[(r0 + 8) * 12 + tig + 4];
            al[t][0] = Alw[r0 * 12 + tig];
            al[t][1] = Alw[(r0 + 8) * 12 + tig];
            al[t][2] = Alw[r0 * 12 + tig + 4];
            al[t][3] = Alw[(r0 + 8) * 12 + tig + 4];
        }
        u32 bf[8][2];
#pragma unroll
        for (int nb = 0; nb < 8; ++nb) {
            int n = wn * 64 + nb * 8 + gid;
            bf[nb][0] = Bhw[n * 12 + tig];
            bf[nb][1] = Bhw[n * 12 + tig + 4];
        }
        // all-hi pass (16 distinct accumulators), then all-lo pass
#pragma unroll
        for (int nb = 0; nb < 8; ++nb) {
            mma16816(c[0][nb], ah[0], bf[nb][0], bf[nb][1]);
            mma16816(c[1][nb], ah[1], bf[nb][0], bf[nb][1]);
        }
#pragma unroll
        for (int nb = 0; nb < 8; ++nb) {
            mma16816(c[0][nb], al[0], bf[nb][0], bf[nb][1]);
            mma16816(c[1][nb], al[1], bf[nb][0], bf[nb][1]);
        }

        if (cs < 15) {
            __half* dst = smh + (buf ^ 1) * BUFH;
            *(uint4*)&dst[soff]        = pah;
            *(uint4*)&dst[3072 + soff] = pal;
            *(uint4*)&dst[6144 + soff] = pbh;
            __syncthreads();
        }
    }

    const float wscale = (mt == 0) ? 0.25f : 1.0f;
    float bias[2][2];
#pragma unroll
    for (int t = 0; t < 2; ++t) {
        int m = wm * 32 + t * 16 + gid;
        if (mt < 3) {
            bias[t][0] = b_qkv[mt * 128 + m] * wscale;
            bias[t][1] = b_qkv[mt * 128 + m + 8] * wscale;
        } else {
            bias[t][0] = b_out[m];
            bias[t][1] = b_out[m + 8];
        }
    }
#pragma unroll
    for (int t = 0; t < 2; ++t)
#pragma unroll
        for (int nb = 0; nb < 8; ++nb) {
            c[t][nb].x += bias[t][0]; c[t][nb].y += bias[t][0];
            c[t][nb].z += bias[t][1]; c[t][nb].w += bias[t][1];
        }

    for (int mc = 0; mc < 4; ++mc) {
        __syncthreads();
        if (wm == mc) {
#pragma unroll
            for (int t = 0; t < 2; ++t)
#pragma unroll
                for (int nb = 0; nb < 8; ++nb) {
                    int col = wn * 64 + nb * 8 + tig * 2;
                    int r0 = t * 16 + gid;
                    *(float2*)&S[r0 * SSTR + col]       = make_float2(c[t][nb].x, c[t][nb].y);
                    *(float2*)&S[(r0 + 8) * SSTR + col] = make_float2(c[t][nb].z, c[t][nb].w);
                }
        }
        __syncthreads();

        if (mt == 3) {
#pragma unroll
            for (int t = 0; t < 4; ++t) {
                int idx = tid + t * 256;
                int nq = idx & 31, row = idx >> 5;
                float4 v = *(const float4*)&S[row * SSTR + nq * 4];
                *(float4*)&out[b * 262144 + (mc * 32 + row) * NPIX + n0 + nq * 4] = v;
            }
        } else if (mt == 2) {
#pragma unroll
            for (int t = 0; t < 2; ++t) {
                int idx = tid + t * 256;
                int noct = idx & 15, row = idx >> 4;
                const float* sp = &S[row * SSTR + noct * 8];
                uint4 u;
                u.x = h2u(__floats2half2_rn(sp[0], sp[1]));
                u.y = h2u(__floats2half2_rn(sp[2], sp[3]));
                u.z = h2u(__floats2half2_rn(sp[4], sp[5]));
                u.w = h2u(__floats2half2_rn(sp[6], sp[7]));
                int h = mc * 2 + (row >> 4);
                int d = row & 15;
                *(uint4*)&g_vt[(((b * 8 + h) * 16 + d) << 10) + n0 + noct * 8] = u;
            }
        } else {
            __half* g = (mt == 0) ? g_qh : g_kh;
#pragma unroll
            for (int t = 0; t < 2; ++t) {
                int idx = tid + t * 256;
                int n = idx & 127;
                int rest = idx >> 7;
                int hsel = rest >> 1, dh = rest & 1;
                int rb = hsel * 16 + dh * 8;
                uint4 u;
                u.x = h2u(__floats2half2_rn(S[(rb + 0) * SSTR + n], S[(rb + 1) * SSTR + n]));
                u.y = h2u(__floats2half2_rn(S[(rb + 2) * SSTR + n], S[(rb + 3) * SSTR + n]));
                u.z = h2u(__floats2half2_rn(S[(rb + 4) * SSTR + n], S[(rb + 5) * SSTR + n]));
                u.w = h2u(__floats2half2_rn(S[(rb + 6) * SSTR + n], S[(rb + 7) * SSTR + n]));
                int bh = b * 8 + mc * 2 + hsel;
                *(uint4*)&g[((u64)bh << 14) + (u64)(n0 + n) * 16 + dh * 8] = u;
            }
        }
    }
}

// ---------------- kernel 2: tensor-core attention (R15-verified) -----------
#define VROW 1032     // halves per Vt row (516 words)
__global__ __launch_bounds__(256, 3) void k_attn()
{
    extern __shared__ __half sm[];
    __half* Ka = sm;                    // [1024][8]  k dims 0..7
    __half* Kb = sm + 8192;             // [1024][8]  k dims 8..15
    __half* Vt = sm + 16384;            // [16][VROW]
    const int qb  = blockIdx.x;
    const int bh  = blockIdx.y;
    const int tid = threadIdx.x;
    const int w   = tid >> 5;
    const int lane = tid & 31;
    const int gid = lane >> 2, tig = lane & 3;
    const u64 ONE = make2(1.0f);

    const uint4* ksrc = (const uint4*)(g_kh + ((u64)bh << 14));
    const uint4* vsrc = (const uint4*)(g_vt + ((u64)bh << 14));
#pragma unroll
    for (int j = 0; j < 8; ++j) {
        int idx = tid + j * 256;
        int seq = idx >> 1, hp = idx & 1;
        __half* kd = hp ? Kb : Ka;
        *(uint4*)&kd[seq * 8] = ksrc[idx];
    }
#pragma unroll
    for (int j = 0; j < 8; ++j) {
        int idx = tid + j * 256;
        int row = idx >> 7, off = (idx & 127) * 8;
        *(uint4*)&Vt[row * VROW + off] = vsrc[idx];
    }

    const __half* qp = g_qh + ((u64)bh << 14) + (qb * 128 + w * 16) * 16;
    u32 aq[4];
    aq[0] = *(const u32*)(qp + gid * 16 + tig * 2);
    aq[1] = *(const u32*)(qp + (gid + 8) * 16 + tig * 2);
    aq[2] = *(const u32*)(qp + gid * 16 + tig * 2 + 8);
    aq[3] = *(const u32*)(qp + (gid + 8) * 16 + tig * 2 + 8);
    __syncthreads();

    float4 o0 = make_float4(0.f, 0.f, 0.f, 0.f);
    float4 o1 = make_float4(0.f, 0.f, 0.f, 0.f);
    u64 l2a = 0ull, l2b = 0ull;

    const u32* kaw = (const u32*)Ka;
    const u32* kbw = (const u32*)Kb;
    const u32* vw  = (const u32*)Vt;

#pragma unroll 2
    for (int n0 = 0; n0 < NPIX; n0 += 16) {
        u32 kb00 = kaw[(n0 + gid) * 4 + tig];
        u32 kb01 = kbw[(n0 + gid) * 4 + tig];
        u32 kb10 = kaw[(n0 + 8 + gid) * 4 + tig];
        u32 kb11 = kbw[(n0 + 8 + gid) * 4 + tig];
        float4 s0 = make_float4(0.f, 0.f, 0.f, 0.f);
        float4 s1 = make_float4(0.f, 0.f, 0.f, 0.f);
        mma16816(s0, aq, kb00, kb01);
        mma16816(s1, aq, kb10, kb11);

        u64 e0 = exp_dual(pack2(s0.x, s0.y));
        u64 e1 = exp_dual(pack2(s0.z, s0.w));
        u64 e2 = exp_dual(pack2(s1.x, s1.y));
        u64 e3 = exp_dual(pack2(s1.z, s1.w));
        l2a = fma2(e0, ONE, l2a); l2a = fma2(e2, ONE, l2a);
        l2b = fma2(e1, ONE, l2b); l2b = fma2(e3, ONE, l2b);

        float2 f0 = unpack2(e0), f1 = unpack2(e1), f2 = unpack2(e2), f3 = unpack2(e3);
        u32 ph[4] = {h2u(__floats2half2_rn(f0.x, f0.y)),
                     h2u(__floats2half2_rn(f1.x, f1.y)),
                     h2u(__floats2half2_rn(f2.x, f2.y)),
                     h2u(__floats2half2_rn(f3.x, f3.y))};

        u32 vb00 = vw[gid * 516 + (n0 >> 1) + tig];
        u32 vb01 = vw[gid * 516 + (n0 >> 1) + tig + 4];
        u32 vb10 = vw[(gid + 8) * 516 + (n0 >> 1) + tig];
        u32 vb11 = vw[(gid + 8) * 516 + (n0 >> 1) + tig + 4];

        mma16816(o0, ph, vb00, vb01);
        mma16816(o1, ph, vb10, vb11);
    }

    float2 lA = unpack2(l2a), lB = unpack2(l2b);
    float lr0 = lA.x + lA.y;
    float lr8 = lB.x + lB.y;
    lr0 += __shfl_xor_sync(0xFFFFFFFFu, lr0, 1);
    lr0 += __shfl_xor_sync(0xFFFFFFFFu, lr0, 2);
    lr8 += __shfl_xor_sync(0xFFFFFFFFu, lr8, 1);
    lr8 += __shfl_xor_sync(0xFFFFFFFFu, lr8, 2);
    float i0 = 1.0f / lr0, i8 = 1.0f / lr8;

    const int b = bh >> 3, h = bh & 7;
    __half* ob = g_attn_h + (u64)b * (NPIX * 128);
    const int seq0 = qb * 128 + w * 16 + gid;
    const int d0 = h * 16 + tig * 2;
    *(u32*)&ob[(u64)seq0 * 128 + d0]           = h2u(__floats2half2_rn(o0.x * i0, o0.y * i0));
    *(u32*)&ob[(u64)seq0 * 128 + d0 + 8]       = h2u(__floats2half2_rn(o1.x * i0, o1.y * i0));
    *(u32*)&ob[(u64)(seq0 + 8) * 128 + d0]     = h2u(__floats2half2_rn(o0.z * i8, o0.w * i8));
    *(u32*)&ob[(u64)(seq0 + 8) * 128 + d0 + 8] = h2u(__floats2half2_rn(o1.z * i8, o1.w * i8));
}

// ---------------- kernel 3: attn output projection on tensor cores ---------
// Double-buffered + reordered MMAs, 8 K-chunks.
__global__ __launch_bounds__(256, 2) void k_attnproj(
    const float* __restrict__ b_attn, float* __restrict__ out)
{
    __shared__ __align__(16) char smraw[36864];
    __half* smh = (__half*)smraw;
    float*  S   = (float*)smraw;

    const int b  = blockIdx.z;
    const int n0 = blockIdx.x * 128;
    const int tid = threadIdx.x;
    const int w    = tid >> 5;
    const int lane = tid & 31;
    const int gid = lane >> 2, tig = lane & 3;
    const int wm = w & 3;
    const int wn = w >> 2;

    const int sm_row = tid >> 1;
    const int sm_hp  = tid & 1;
    const int soff = sm_row * 24 + sm_hp * 8;

    const __half* asrc = g_attn_h + (u64)b * (NPIX * 128);
    const int aoff = sm_row * 16 + sm_hp * 8;
    const u64 boff = (u64)(n0 + sm_row) * 128 + sm_hp * 8;

    {
        uint4 pah = *(const uint4*)&g_wah[aoff];
        uint4 pal = *(const uint4*)&g_wal[aoff];
        uint4 pbh = *(const uint4*)&asrc[boff];
        *(uint4*)&smh[soff]        = pah;
        *(uint4*)&smh[3072 + soff] = pal;
        *(uint4*)&smh[6144 + soff] = pbh;
    }
    __syncthreads();

    float4 c[2][8];
#pragma unroll
    for (int t = 0; t < 2; ++t)
#pragma unroll
        for (int nb = 0; nb < 8; ++nb) c[t][nb] = make_float4(0.f, 0.f, 0.f, 0.f);

    for (int cs = 0; cs < 8; ++cs) {
        const int buf = cs & 1;
        uint4 pah, pal, pbh;
        if (cs < 7) {
            pah = *(const uint4*)&g_wah[(cs + 1) * 128 * 16 + aoff];
            pal = *(const uint4*)&g_wal[(cs + 1) * 128 * 16 + aoff];
            pbh = *(const uint4*)&asrc[boff + (cs + 1) * 16];
        }

        const u32* Ahw = (const u32*)(smh + buf * BUFH);
        const u32* Alw = (const u32*)(smh + buf * BUFH + 3072);
        const u32* Bhw = (const u32*)(smh + buf * BUFH + 6144);

        u32 ah[2][4], al[2][4];
#pragma unroll
        for (int t = 0; t < 2; ++t) {
            int r0 = wm * 32 + t * 16 + gid;
            ah[t][0] = Ahw[r0 * 12 + tig];
            ah[t][1] = Ahw[(r0 + 8) * 12 + tig];
            ah[t][2] = Ahw[r0 * 12 + tig + 4];
            ah[t][3] = Ahw[(r0 + 8) * 12 + tig + 4];
            al[t][0] = Alw[r0 * 12 + tig];
            al[t][1] = Alw[(r0 + 8) * 12 + tig];
            al[t][2] = Alw[r0 * 12 + tig + 4];
            al[t][3] = Alw[(r0 + 8) * 12 + tig + 4];
        }
        u32 bf[8][2];
#pragma unroll
        for (int nb = 0; nb < 8; ++nb) {
            int n = wn * 64 + nb * 8 + gid;
            bf[nb][0] = Bhw[n * 12 + tig];
            bf[nb][1] = Bhw[n * 12 + tig + 4];
        }
#pragma unroll
        for (int nb = 0; nb < 8; ++nb) {
            mma16816(c[0][nb], ah[0], bf[nb][0], bf[nb][1]);
            mma16816(c[1][nb], ah[1], bf[nb][0], bf[nb][1]);
        }
#pragma unroll
        for (int nb = 0; nb < 8; ++nb) {
            mma16816(c[0][nb], al[0], bf[nb][0], bf[nb][1]);
            mma16816(c[1][nb], al[1], bf[nb][0], bf[nb][1]);
        }

        if (cs < 7) {
            __half* dst = smh + (buf ^ 1) * BUFH;
            *(uint4*)&dst[soff]        = pah;
            *(uint4*)&dst[3072 + soff] = pal;
            *(uint4*)&dst[6144 + soff] = pbh;
            __syncthreads();
        }
    }

    float bias[2][2];
#pragma unroll
    for (int t = 0; t < 2; ++t) {
        int m = wm * 32 + t * 16 + gid;
        bias[t][0] = b_attn[m];
        bias[t][1] = b_attn[m + 8];
    }
#pragma unroll
    for (int t = 0; t < 2; ++t)
#pragma unroll
        for (int nb = 0; nb < 8; ++nb) {
            c[t][nb].x += bias[t][0]; c[t][nb].y += bias[t][0];
            c[t][nb].z += bias[t][1]; c[t][nb].w += bias[t][1];
        }

    for (int mc = 0; mc < 4; ++mc) {
        __syncthreads();
        if (wm == mc) {
#pragma unroll
            for (int t = 0; t < 2; ++t)
#pragma unroll
                for (int nb = 0; nb < 8; ++nb) {
                    int col = wn * 64 + nb * 8 + tig * 2;
                    int r0 = t * 16 + gid;
                    *(float2*)&S[r0 * SSTR + col]       = make_float2(c[t][nb].x, c[t][nb].y);
                    *(float2*)&S[(r0 + 8) * SSTR + col] = make_float2(c[t][nb].z, c[t][nb].w);
                }
        }
        __syncthreads();
#pragma unroll
        for (int t = 0; t < 4; ++t) {
            int idx = tid + t * 256;
            int nq = idx & 31, row = idx >> 5;
            float4 v = *(const float4*)&S[row * SSTR + nq * 4];
            *(float4*)&out[b * 262144 + (128 + mc * 32 + row) * NPIX + n0 + nq * 4] = v;
        }
    }
}

// ---------------- launch ----------------------------------------------------
extern "C" void kernel_launch(void* const* d_in, const int* in_sizes, int n_in,
                              void* d_out, int out_size)
{
    const float* x      = (const float*)d_in[0];
    const float* w_qkv  = (const float*)d_in[1];
    const float* b_qkv  = (const float*)d_in[2];
    const float* w_attn = (const float*)d_in[3];
    const float* b_attn = (const float*)d_in[4];
    const float* w_out  = (const float*)d_in[5];
    const float* b_out  = (const float*)d_in[6];
    float* out = (float*)d_out;

    k_cvt_w<<<512, 64>>>(w_qkv, w_out);
    k_cvt_wa<<<128, 32>>>(w_attn);
    dim3 gc(64, 32);
    k_cvt_x<<<gc, 256>>>(x);

    dim3 g1(8, 4, 32);                 // n-tiles(128), m-tiles(q/k/v/conv), batch
    k_proj<<<g1, 256>>>(b_qkv, b_out, out);

    const int smem_attn = (1024 * 16 + 16 * VROW) * (int)sizeof(__half); // 65792
    cudaFuncSetAttribute(k_attn, cudaFuncAttributeMaxDynamicSharedMemorySize,
                         smem_attn);
    dim3 g2(8, 256);                   // q-blocks x (b,h)
    k_attn<<<g2, 256, smem_attn>>>();

    dim3 g3(8, 1, 32);
    k_attnproj<<<g3, 256>>>(b_attn, out);
}